// round 2
// baseline (speedup 1.0000x reference)
#include <cuda_runtime.h>
#include <math.h>
#include <stdint.h>
#include <stddef.h>

#define Bb 32
#define Tt 512
#define Dd 256
#define Hh 1024
#define G4 4096
#define BT (Bb*Tt)          // 16384
#define NCTA 128
#define UPC 8               // hidden units per CTA

// ---------------- scratch (device globals; no allocation allowed) ----------------
__device__ float g_xg[(size_t)BT * G4];   // 256 MB: gate preactivations / reused as act+lin
__device__ float g_hseq[(size_t)BT * Hh]; // 64 MB: per-layer output sequence
__device__ float g_hbuf[2 * Hh * Bb];     // recurrent h double buffer, layout [parity][unit][batch]
__device__ unsigned int g_cnt;            // grid barrier counter

#define SCAN_SMEM ((32*1024 + 128*33 + 1024) * 4)   // W slice + h chunk + xg stage = 152064 B

// ---------------- helpers ----------------
__device__ __forceinline__ float sigm(float x) { return 1.f / (1.f + expf(-x)); }
__device__ __forceinline__ float gelu_exact(float x) {
    return 0.5f * x * (1.f + erff(x * 0.70710678118654752440f));
}

// ---------------- reset (barrier counter + h double buffer) ----------------
__global__ void reset_scan_state() {
    int i = blockIdx.x * blockDim.x + threadIdx.x;
    if (i == 0) g_cnt = 0u;
    for (int j = i; j < 2 * Hh * Bb; j += gridDim.x * blockDim.x) g_hbuf[j] = 0.f;
}

// ---------------- fp32 GEMM: C[m][n] = sum_k A[m][k]*Bw[n][k] + b1[n] (+ b2[n]) ----------------
// M,N multiples of 128; K multiple of 8.
__global__ void __launch_bounds__(256) gemm_nt_bias(
    const float* __restrict__ A, const float* __restrict__ Bw,
    const float* __restrict__ b1, const float* __restrict__ b2,
    float* __restrict__ C, int M, int N, int K)
{
    __shared__ float As[8][132];
    __shared__ float Bs[8][132];
    const int tid = threadIdx.x;
    const int bm = blockIdx.y << 7;
    const int bn = blockIdx.x << 7;
    const int tx = tid & 15;       // 16 cols of threads
    const int ty = tid >> 4;       // 16 rows of threads
    const int lrow = tid >> 1;     // 0..127 (tile row loaded by this thread)
    const int lc4  = (tid & 1) << 2;

    const float* Ap = A + (size_t)(bm + lrow) * K + lc4;
    const float* Bp = Bw + (size_t)(bn + lrow) * K + lc4;

    float acc[8][8];
#pragma unroll
    for (int i = 0; i < 8; i++)
#pragma unroll
        for (int j = 0; j < 8; j++) acc[i][j] = 0.f;

    for (int k0 = 0; k0 < K; k0 += 8) {
        float4 av = *(const float4*)(Ap + k0);
        float4 bv = *(const float4*)(Bp + k0);
        As[lc4+0][lrow] = av.x; As[lc4+1][lrow] = av.y;
        As[lc4+2][lrow] = av.z; As[lc4+3][lrow] = av.w;
        Bs[lc4+0][lrow] = bv.x; Bs[lc4+1][lrow] = bv.y;
        Bs[lc4+2][lrow] = bv.z; Bs[lc4+3][lrow] = bv.w;
        __syncthreads();
#pragma unroll
        for (int k = 0; k < 8; k++) {
            float4 a0 = *(const float4*)&As[k][ty*8];
            float4 a1 = *(const float4*)&As[k][ty*8+4];
            float4 c0 = *(const float4*)&Bs[k][tx*8];
            float4 c1 = *(const float4*)&Bs[k][tx*8+4];
            float a[8] = {a0.x,a0.y,a0.z,a0.w,a1.x,a1.y,a1.z,a1.w};
            float b[8] = {c0.x,c0.y,c0.z,c0.w,c1.x,c1.y,c1.z,c1.w};
#pragma unroll
            for (int i = 0; i < 8; i++)
#pragma unroll
                for (int j = 0; j < 8; j++) acc[i][j] += a[i] * b[j];
        }
        __syncthreads();
    }

    float bs[8];
#pragma unroll
    for (int j = 0; j < 8; j++) {
        int n = bn + tx*8 + j;
        bs[j] = b1[n] + (b2 ? b2[n] : 0.f);
    }
#pragma unroll
    for (int i = 0; i < 8; i++) {
        float* cp = C + (size_t)(bm + ty*8 + i) * N + bn + tx*8;
#pragma unroll
        for (int j = 0; j < 8; j++) cp[j] = acc[i][j] + bs[j];
    }
}

// ---------------- persistent LSTM scan ----------------
// 128 CTAs x 256 threads; CTA c owns units [c*8, c*8+8).
// thread: uu = tid>>5 (warp == unit), b = tid&31 (lane == batch).
__global__ void __launch_bounds__(256, 1) lstm_scan(
    const float* __restrict__ W_hh,   // [4H][H]
    const float* __restrict__ xg,     // [B][T][4H] precomputed gates (+biases)
    float* __restrict__ hseq)         // [B][T][H] output sequence
{
    extern __shared__ float smem[];
    float* sW  = smem;                // 32*1024  (rows: uu*4+gate)
    float* sH  = smem + 32*1024;      // 128*33   (h chunk, [k][b], pad 33)
    float* sXG = sH + 128*33;         // 1024     ([b][gate][u])

    const int tid = threadIdx.x;
    const int u0  = blockIdx.x * UPC;

    // Load this CTA's W_hh slice into SMEM: row r = uu*4+g  <-  W_hh[g*H + u0+uu][*]
    for (int i = tid; i < 32*256; i += 256) {   // 8192 float4
        int r  = i >> 8;
        int c4 = (i & 255) << 2;
        int uu = r >> 2, g = r & 3;
        float4 v = *(const float4*)(W_hh + (size_t)(g*Hh + u0 + uu) * Hh + c4);
        *(float4*)(sW + r*1024 + c4) = v;
    }

    const int uu = tid >> 5;
    const int b  = tid & 31;
    const float* sW0 = sW + (uu*4+0)*1024;
    const float* sW1 = sW + (uu*4+1)*1024;
    const float* sW2 = sW + (uu*4+2)*1024;
    const float* sW3 = sW + (uu*4+3)*1024;

    // xg staging mapping: thread -> (batch pb, gate pg, 4-unit half ph)
    const int pb = tid >> 3;
    const int pg = (tid >> 1) & 3;
    const int ph = (tid & 1) << 2;
    const float* xg_base = xg + (size_t)pb * Tt * G4 + pg*1024 + u0 + ph;
    float4 px = *(const float4*)xg_base;   // prefetch t = 0

    float c_state = 0.f;
    unsigned bar = 0;

    for (int t = 0; t < Tt; t++) {
        // stage prefetched xg for this step; kick off next step's load
        {
            float* d = sXG + pb*32 + pg*8 + ph;
            d[0] = px.x; d[1] = px.y; d[2] = px.z; d[3] = px.w;
            int tn = (t + 1 < Tt) ? (t + 1) : t;
            px = *(const float4*)(xg_base + (size_t)tn * G4);
        }

        float a0 = 0.f, a1 = 0.f, a2 = 0.f, a3 = 0.f;
        const int rp = t & 1;
        const float* hprev = g_hbuf + rp * (Hh * Bb);

        for (int k0 = 0; k0 < Hh; k0 += 128) {
            // stage 128x32 h chunk (coalesced gmem, conflict-free smem)
#pragma unroll
            for (int i = 0; i < 4; i++) {
                int e  = tid + i*256;          // float4 index 0..1023
                int kk = e >> 3;
                int b4 = (e & 7) << 2;
                float4 hv = __ldcg((const float4*)(hprev + (k0 + kk)*Bb + b4));
                float* d = sH + kk*33 + b4;
                d[0] = hv.x; d[1] = hv.y; d[2] = hv.z; d[3] = hv.w;
            }
            __syncthreads();
#pragma unroll
            for (int kk = 0; kk < 32; kk++) {
                const int k = kk << 2;
                float4 wi = *(const float4*)(sW0 + k0 + k);
                float4 wf = *(const float4*)(sW1 + k0 + k);
                float4 wg = *(const float4*)(sW2 + k0 + k);
                float4 wo = *(const float4*)(sW3 + k0 + k);
                float h0v = sH[(k+0)*33 + b];
                float h1v = sH[(k+1)*33 + b];
                float h2v = sH[(k+2)*33 + b];
                float h3v = sH[(k+3)*33 + b];
                a0 += wi.x*h0v; a0 += wi.y*h1v; a0 += wi.z*h2v; a0 += wi.w*h3v;
                a1 += wf.x*h0v; a1 += wf.y*h1v; a1 += wf.z*h2v; a1 += wf.w*h3v;
                a2 += wg.x*h0v; a2 += wg.y*h1v; a2 += wg.z*h2v; a2 += wg.w*h3v;
                a3 += wo.x*h0v; a3 += wo.y*h1v; a3 += wo.z*h2v; a3 += wo.w*h3v;
            }
            __syncthreads();
        }

        // add precomputed input gates
        a0 += sXG[b*32 + 0*8 + uu];
        a1 += sXG[b*32 + 1*8 + uu];
        a2 += sXG[b*32 + 2*8 + uu];
        a3 += sXG[b*32 + 3*8 + uu];

        float ig = sigm(a0);
        float fg = sigm(a1);
        float gg = tanhf(a2);
        float og = sigm(a3);
        c_state = fg * c_state + ig * gg;
        float hval = og * tanhf(c_state);

        // write new h (coalesced; .cg to stay L2-coherent across CTAs)
        __stcg(g_hbuf + (1 - rp) * (Hh * Bb) + (u0 + uu)*Bb + b, hval);
        hseq[((size_t)b * Tt + t) * Hh + u0 + uu] = hval;

        // grid barrier (all 128 CTAs resident by construction)
        __syncthreads();
        if (tid == 0) {
            __threadfence();
            atomicAdd(&g_cnt, 1u);
            bar += NCTA;
            while (*((volatile unsigned int*)&g_cnt) < bar) { }
            __threadfence();
        }
        __syncthreads();
    }
}

// ---------------- LayerNorm -> GELU (one block per row) ----------------
__global__ void ln_gelu_kernel(const float* __restrict__ X, const float* __restrict__ w,
                               const float* __restrict__ bv, float* __restrict__ Y)
{
    __shared__ float red[2][8];
    const int row = blockIdx.x;
    const int tid = threadIdx.x;
    float4 v = ((const float4*)(X + (size_t)row * Hh))[tid];
    float s = v.x + v.y + v.z + v.w;
    float q = v.x*v.x + v.y*v.y + v.z*v.z + v.w*v.w;
    int lane = tid & 31, wid = tid >> 5;
#pragma unroll
    for (int o = 16; o; o >>= 1) {
        s += __shfl_xor_sync(0xffffffffu, s, o);
        q += __shfl_xor_sync(0xffffffffu, q, o);
    }
    if (lane == 0) { red[0][wid] = s; red[1][wid] = q; }
    __syncthreads();
    if (wid == 0) {
        s = (lane < 8) ? red[0][lane] : 0.f;
        q = (lane < 8) ? red[1][lane] : 0.f;
#pragma unroll
        for (int o = 4; o; o >>= 1) {
            s += __shfl_xor_sync(0xffffffffu, s, o);
            q += __shfl_xor_sync(0xffffffffu, q, o);
        }
        if (lane == 0) { red[0][0] = s; red[1][0] = q; }
    }
    __syncthreads();
    float mu  = red[0][0] * (1.f / Hh);
    float var = red[1][0] * (1.f / Hh) - mu * mu;
    float rstd = rsqrtf(var + 1e-5f);
    float4 wv = ((const float4*)w)[tid];
    float4 bb = ((const float4*)bv)[tid];
    float4 y;
    y.x = gelu_exact((v.x - mu) * rstd * wv.x + bb.x);
    y.y = gelu_exact((v.y - mu) * rstd * wv.y + bb.y);
    y.z = gelu_exact((v.z - mu) * rstd * wv.z + bb.z);
    y.w = gelu_exact((v.w - mu) * rstd * wv.w + bb.w);
    ((float4*)(Y + (size_t)row * Hh))[tid] = y;
}

// ---------------- GELU -> LayerNorm (one block per row) ----------------
__global__ void gelu_ln_kernel(const float* __restrict__ X, const float* __restrict__ w,
                               const float* __restrict__ bv, float* __restrict__ Y)
{
    __shared__ float red[2][8];
    const int row = blockIdx.x;
    const int tid = threadIdx.x;
    float4 v = ((const float4*)(X + (size_t)row * Hh))[tid];
    v.x = gelu_exact(v.x); v.y = gelu_exact(v.y);
    v.z = gelu_exact(v.z); v.w = gelu_exact(v.w);
    float s = v.x + v.y + v.z + v.w;
    float q = v.x*v.x + v.y*v.y + v.z*v.z + v.w*v.w;
    int lane = tid & 31, wid = tid >> 5;
#pragma unroll
    for (int o = 16; o; o >>= 1) {
        s += __shfl_xor_sync(0xffffffffu, s, o);
        q += __shfl_xor_sync(0xffffffffu, q, o);
    }
    if (lane == 0) { red[0][wid] = s; red[1][wid] = q; }
    __syncthreads();
    if (wid == 0) {
        s = (lane < 8) ? red[0][lane] : 0.f;
        q = (lane < 8) ? red[1][lane] : 0.f;
#pragma unroll
        for (int o = 4; o; o >>= 1) {
            s += __shfl_xor_sync(0xffffffffu, s, o);
            q += __shfl_xor_sync(0xffffffffu, q, o);
        }
        if (lane == 0) { red[0][0] = s; red[1][0] = q; }
    }
    __syncthreads();
    float mu  = red[0][0] * (1.f / Hh);
    float var = red[1][0] * (1.f / Hh) - mu * mu;
    float rstd = rsqrtf(var + 1e-5f);
    float4 wv = ((const float4*)w)[tid];
    float4 bb = ((const float4*)bv)[tid];
    float4 y;
    y.x = (v.x - mu) * rstd * wv.x + bb.x;
    y.y = (v.y - mu) * rstd * wv.y + bb.y;
    y.z = (v.z - mu) * rstd * wv.z + bb.z;
    y.w = (v.w - mu) * rstd * wv.w + bb.w;
    ((float4*)(Y + (size_t)row * Hh))[tid] = y;
}

// ---------------- driver ----------------
extern "C" void kernel_launch(void* const* d_in, const int* in_sizes, int n_in,
                              void* d_out, int out_size)
{
    const float* bone  = (const float*)d_in[0];
    const float* W_ih0 = (const float*)d_in[1];
    const float* W_hh0 = (const float*)d_in[2];
    const float* b_ih0 = (const float*)d_in[3];
    const float* b_hh0 = (const float*)d_in[4];
    const float* W_ih1 = (const float*)d_in[5];
    const float* W_hh1 = (const float*)d_in[6];
    const float* b_ih1 = (const float*)d_in[7];
    const float* b_hh1 = (const float*)d_in[8];
    const float* ln1w  = (const float*)d_in[9];
    const float* ln1b  = (const float*)d_in[10];
    const float* linw  = (const float*)d_in[11];
    const float* linb  = (const float*)d_in[12];
    const float* ln2w  = (const float*)d_in[13];
    const float* ln2b  = (const float*)d_in[14];
    float* out = (float*)d_out;

    float *xg = nullptr, *hseq = nullptr;
    cudaGetSymbolAddress((void**)&xg, g_xg);
    cudaGetSymbolAddress((void**)&hseq, g_hseq);
    float* act = xg;                               // reuse after gates consumed
    float* lin = xg + (size_t)BT * Hh;             // disjoint region

    cudaFuncSetAttribute(lstm_scan, cudaFuncAttributeMaxDynamicSharedMemorySize, SCAN_SMEM);

    dim3 gemm_g4(G4/128, BT/128);
    dim3 gemm_h(Hh/128, BT/128);

    // layer 0
    gemm_nt_bias<<<gemm_g4, 256>>>(bone, W_ih0, b_ih0, b_hh0, xg, BT, G4, Dd);
    reset_scan_state<<<64, 256>>>();
    lstm_scan<<<NCTA, 256, SCAN_SMEM>>>(W_hh0, xg, hseq);

    // layer 1
    gemm_nt_bias<<<gemm_g4, 256>>>(hseq, W_ih1, b_ih1, b_hh1, xg, BT, G4, Hh);
    reset_scan_state<<<64, 256>>>();
    lstm_scan<<<NCTA, 256, SCAN_SMEM>>>(W_hh1, xg, hseq);

    // post: LN -> GELU -> Linear -> GELU -> LN
    ln_gelu_kernel<<<BT, 256>>>(hseq, ln1w, ln1b, act);
    gemm_nt_bias<<<gemm_h, 256>>>(act, linw, linb, nullptr, lin, BT, Hh, Hh);
    gelu_ln_kernel<<<BT, 256>>>(lin, ln2w, ln2b, out);
}

// round 3
// speedup vs baseline: 2.2710x; 2.2710x over previous
#include <cuda_runtime.h>
#include <math.h>
#include <stdint.h>
#include <stddef.h>

#define Bb 32
#define Tt 512
#define Dd 256
#define Hh 1024
#define G4 4096
#define BT (Bb*Tt)          // 16384
#define NCTA 128

// ---------------- scratch (device globals; no allocation allowed) ----------------
__device__ float g_xg[(size_t)BT * G4];     // 256 MB: gate preactivations / reuse
__device__ float g_hseq[(size_t)BT * Hh];   // 64 MB: per-layer output sequence
__device__ float g_hfrag[2 * Hh * Bb];      // h double buffer, tf32 bits, B-fragment layout
__device__ float g_wf0[(size_t)G4 * Hh];    // W_hh0 in A-fragment layout (tf32 bits), 16 MB
__device__ float g_wf1[(size_t)G4 * Hh];    // W_hh1 likewise
__device__ unsigned int g_cnt;              // grid barrier counter

#define PART_STRIDE 1056    // 32 rows * 33 (padded)
#define SCAN_SMEM ((32*1024 + 8*PART_STRIDE + 1024) * 4)   // W frags + partials + xg stage

// ---------------- helpers ----------------
__device__ __forceinline__ float sigm(float x) { return 1.f / (1.f + expf(-x)); }
__device__ __forceinline__ float gelu_exact(float x) {
    return 0.5f * x * (1.f + erff(x * 0.70710678118654752440f));
}
__device__ __forceinline__ unsigned tf32_rna(float x) {
    unsigned r; asm("cvt.rna.tf32.f32 %0, %1;" : "=r"(r) : "f"(x)); return r;
}
__device__ __forceinline__ void mma_tf32(float c[4], const unsigned a[4],
                                         unsigned b0, unsigned b1) {
    asm("mma.sync.aligned.m16n8k8.row.col.f32.tf32.tf32.f32 "
        "{%0,%1,%2,%3},{%4,%5,%6,%7},{%8,%9},{%0,%1,%2,%3};"
        : "+f"(c[0]), "+f"(c[1]), "+f"(c[2]), "+f"(c[3])
        : "r"(a[0]), "r"(a[1]), "r"(a[2]), "r"(a[3]), "r"(b0), "r"(b1));
}

// ---------------- prep: W_hh[4H][H] -> per-CTA mma A-fragment layout ----------------
// out element (c, kk, mt, lane, j):
//   r_local = mt*16 + (lane>>2) + ((j&1)<<3)   (CTA-local gate-row, 0..31; r = g*8+uu)
//   k       = kk*8 + (lane&3) + ((j>>1)<<2)
//   W row   = (r_local>>3)*1024 + c*8 + (r_local&7)
__global__ void prep_whh(const float* __restrict__ W, float* __restrict__ out) {
    int idx = blockIdx.x * 256 + threadIdx.x;       // 1,048,576 threads
    int lane = idx & 31;
    int mt   = (idx >> 5) & 1;
    int kk   = (idx >> 6) & 127;
    int c    = idx >> 13;
    float tmp[4];
#pragma unroll
    for (int j = 0; j < 4; j++) {
        int rl = mt*16 + (lane >> 2) + ((j & 1) << 3);
        int k  = kk*8 + (lane & 3) + ((j >> 1) << 2);
        int R  = (rl >> 3) * 1024 + c*8 + (rl & 7);
        tmp[j] = __uint_as_float(tf32_rna(W[(size_t)R * Hh + k]));
    }
    ((float4*)out)[idx] = make_float4(tmp[0], tmp[1], tmp[2], tmp[3]);
}

// ---------------- reset (barrier counter + h fragment double buffer) ----------------
__global__ void reset_scan_state() {
    int i = blockIdx.x * blockDim.x + threadIdx.x;
    if (i == 0) g_cnt = 0u;
    for (int j = i; j < 2 * Hh * Bb; j += gridDim.x * blockDim.x) g_hfrag[j] = 0.f;
}

// ---------------- fp32 GEMM: C[m][n] = sum_k A[m][k]*Bw[n][k] + b1[n] (+ b2[n]) ----------------
__global__ void __launch_bounds__(256) gemm_nt_bias(
    const float* __restrict__ A, const float* __restrict__ Bw,
    const float* __restrict__ b1, const float* __restrict__ b2,
    float* __restrict__ C, int M, int N, int K)
{
    __shared__ float As[8][132];
    __shared__ float Bs[8][132];
    const int tid = threadIdx.x;
    const int bm = blockIdx.y << 7;
    const int bn = blockIdx.x << 7;
    const int tx = tid & 15;
    const int ty = tid >> 4;
    const int lrow = tid >> 1;
    const int lc4  = (tid & 1) << 2;

    const float* Ap = A + (size_t)(bm + lrow) * K + lc4;
    const float* Bp = Bw + (size_t)(bn + lrow) * K + lc4;

    float acc[8][8];
#pragma unroll
    for (int i = 0; i < 8; i++)
#pragma unroll
        for (int j = 0; j < 8; j++) acc[i][j] = 0.f;

    for (int k0 = 0; k0 < K; k0 += 8) {
        float4 av = *(const float4*)(Ap + k0);
        float4 bv = *(const float4*)(Bp + k0);
        As[lc4+0][lrow] = av.x; As[lc4+1][lrow] = av.y;
        As[lc4+2][lrow] = av.z; As[lc4+3][lrow] = av.w;
        Bs[lc4+0][lrow] = bv.x; Bs[lc4+1][lrow] = bv.y;
        Bs[lc4+2][lrow] = bv.z; Bs[lc4+3][lrow] = bv.w;
        __syncthreads();
#pragma unroll
        for (int k = 0; k < 8; k++) {
            float4 a0 = *(const float4*)&As[k][ty*8];
            float4 a1 = *(const float4*)&As[k][ty*8+4];
            float4 c0 = *(const float4*)&Bs[k][tx*8];
            float4 c1 = *(const float4*)&Bs[k][tx*8+4];
            float a[8] = {a0.x,a0.y,a0.z,a0.w,a1.x,a1.y,a1.z,a1.w};
            float b[8] = {c0.x,c0.y,c0.z,c0.w,c1.x,c1.y,c1.z,c1.w};
#pragma unroll
            for (int i = 0; i < 8; i++)
#pragma unroll
                for (int j = 0; j < 8; j++) acc[i][j] += a[i] * b[j];
        }
        __syncthreads();
    }

    float bs[8];
#pragma unroll
    for (int j = 0; j < 8; j++) {
        int n = bn + tx*8 + j;
        bs[j] = b1[n] + (b2 ? b2[n] : 0.f);
    }
#pragma unroll
    for (int i = 0; i < 8; i++) {
        float* cp = C + (size_t)(bm + ty*8 + i) * N + bn + tx*8;
#pragma unroll
        for (int j = 0; j < 8; j++) cp[j] = acc[i][j] + bs[j];
    }
}

// ---------------- persistent LSTM scan (tf32 tensor-core recurrence) ----------------
// 128 CTAs x 256 threads. CTA c owns units [c*8, c*8+8) -> 32 gate-rows.
// mma phase: warp kg (0..7) handles K-chunk [kg*128, kg*128+128) over M=32, N=32.
// pointwise: thread = (uu = tid>>5, b = lane).
__global__ void __launch_bounds__(256, 1) lstm_scan(
    const float* __restrict__ wf,     // this layer's W in A-fragment layout
    const float* __restrict__ xg,     // [B][T][4H] precomputed input gates (+biases)
    float* __restrict__ hseq)         // [B][T][H]
{
    extern __shared__ float smem[];
    float* sW   = smem;                 // 32768 floats (A fragments)
    float* part = smem + 32768;         // 8448 floats: part[kg][r][n], stride 33
    float* sXG  = part + 8*PART_STRIDE; // 1024 floats: [b][gate][u]

    const int tid  = threadIdx.x;
    const int lane = tid & 31;
    const int kg   = tid >> 5;
    const int u0   = blockIdx.x * 8;

    // load this CTA's W fragment slice (already tf32 bits, frag order)
    {
        const float4* wsrc = (const float4*)(wf + (size_t)blockIdx.x * 32768);
        float4* wdst = (float4*)sW;
        for (int i = tid; i < 8192; i += 256) wdst[i] = wsrc[i];
    }

    // xg staging mapping: thread -> (batch pb, gate pg, 4-unit half ph)
    const int pb = tid >> 3;
    const int pg = (tid >> 1) & 3;
    const int ph = (tid & 1) << 2;
    const float* xg_base = xg + (size_t)pb * Tt * G4 + pg*1024 + u0 + ph;
    float4 px = *(const float4*)xg_base;   // prefetch t = 0

    const int uu = tid >> 5;
    const int b  = lane;
    float c_state = 0.f;
    unsigned bar = 0;
    __syncthreads();

    for (int t = 0; t < Tt; t++) {
        // stage this step's xg, prefetch next
        {
            float* d = sXG + pb*32 + pg*8 + ph;
            d[0] = px.x; d[1] = px.y; d[2] = px.z; d[3] = px.w;
            int tn = (t + 1 < Tt) ? (t + 1) : t;
            px = *(const float4*)(xg_base + (size_t)tn * G4);
        }

        const int rp = t & 1;
        const float* hb = g_hfrag + rp * (Hh * Bb);

        float acc[2][4][4];
#pragma unroll
        for (int mt = 0; mt < 2; mt++)
#pragma unroll
            for (int nt = 0; nt < 4; nt++)
#pragma unroll
                for (int j = 0; j < 4; j++) acc[mt][nt][j] = 0.f;

#pragma unroll 4
        for (int ks = 0; ks < 16; ks++) {
            const int kk = kg*16 + ks;
            float4 wa0 = ((const float4*)sW)[(kk*2+0)*32 + lane];
            float4 wa1 = ((const float4*)sW)[(kk*2+1)*32 + lane];
            unsigned A0[4] = {__float_as_uint(wa0.x), __float_as_uint(wa0.y),
                              __float_as_uint(wa0.z), __float_as_uint(wa0.w)};
            unsigned A1[4] = {__float_as_uint(wa1.x), __float_as_uint(wa1.y),
                              __float_as_uint(wa1.z), __float_as_uint(wa1.w)};
            float2 bv[4];
#pragma unroll
            for (int nt = 0; nt < 4; nt++)
                bv[nt] = __ldcg((const float2*)(hb + ((size_t)(kk*4+nt)*32 + lane)*2));
#pragma unroll
            for (int nt = 0; nt < 4; nt++) {
                unsigned b0 = __float_as_uint(bv[nt].x);
                unsigned b1 = __float_as_uint(bv[nt].y);
                mma_tf32(acc[0][nt], A0, b0, b1);
                mma_tf32(acc[1][nt], A1, b0, b1);
            }
        }

        // store K-group partials (c-fragment scatter)
#pragma unroll
        for (int mt = 0; mt < 2; mt++)
#pragma unroll
            for (int nt = 0; nt < 4; nt++)
#pragma unroll
                for (int j = 0; j < 4; j++) {
                    int r = mt*16 + (lane >> 2) + ((j >> 1) << 3);
                    int n = nt*8 + ((lane & 3) << 1) + (j & 1);
                    part[kg*PART_STRIDE + r*33 + n] = acc[mt][nt][j];
                }
        __syncthreads();

        // pointwise LSTM cell update: thread (uu, b)
        float ga[4];
#pragma unroll
        for (int g = 0; g < 4; g++) {
            int r = g*8 + uu;
            float s = 0.f;
#pragma unroll
            for (int q = 0; q < 8; q++) s += part[q*PART_STRIDE + r*33 + b];
            ga[g] = s + sXG[b*32 + g*8 + uu];
        }
        float ig = sigm(ga[0]);
        float fg = sigm(ga[1]);
        float gg = tanhf(ga[2]);
        float og = sigm(ga[3]);
        c_state = fg * c_state + ig * gg;
        float hval = og * tanhf(c_state);

        // write h into B-fragment layout (tf32 bits) + raw hseq
        int u = u0 + uu;
        int pos = ((u >> 3)*4 + (b >> 3))*64 + ((b & 7)*4 + (u & 3))*2 + ((u >> 2) & 1);
        __stcg(g_hfrag + (1 - rp)*(Hh*Bb) + pos, __uint_as_float(tf32_rna(hval)));
        hseq[((size_t)b * Tt + t) * Hh + u] = hval;

        // grid barrier (128 CTAs, all resident)
        __syncthreads();
        if (tid == 0) {
            __threadfence();
            atomicAdd(&g_cnt, 1u);
            bar += NCTA;
            while (*((volatile unsigned int*)&g_cnt) < bar) { }
            __threadfence();
        }
        __syncthreads();
    }
}

// ---------------- LayerNorm -> GELU (one block per row) ----------------
__global__ void ln_gelu_kernel(const float* __restrict__ X, const float* __restrict__ w,
                               const float* __restrict__ bv, float* __restrict__ Y)
{
    __shared__ float red[2][8];
    const int row = blockIdx.x;
    const int tid = threadIdx.x;
    float4 v = ((const float4*)(X + (size_t)row * Hh))[tid];
    float s = v.x + v.y + v.z + v.w;
    float q = v.x*v.x + v.y*v.y + v.z*v.z + v.w*v.w;
    int lane = tid & 31, wid = tid >> 5;
#pragma unroll
    for (int o = 16; o; o >>= 1) {
        s += __shfl_xor_sync(0xffffffffu, s, o);
        q += __shfl_xor_sync(0xffffffffu, q, o);
    }
    if (lane == 0) { red[0][wid] = s; red[1][wid] = q; }
    __syncthreads();
    if (wid == 0) {
        s = (lane < 8) ? red[0][lane] : 0.f;
        q = (lane < 8) ? red[1][lane] : 0.f;
#pragma unroll
        for (int o = 4; o; o >>= 1) {
            s += __shfl_xor_sync(0xffffffffu, s, o);
            q += __shfl_xor_sync(0xffffffffu, q, o);
        }
        if (lane == 0) { red[0][0] = s; red[1][0] = q; }
    }
    __syncthreads();
    float mu  = red[0][0] * (1.f / Hh);
    float var = red[1][0] * (1.f / Hh) - mu * mu;
    float rstd = rsqrtf(var + 1e-5f);
    float4 wv = ((const float4*)w)[tid];
    float4 bb = ((const float4*)bv)[tid];
    float4 y;
    y.x = gelu_exact((v.x - mu) * rstd * wv.x + bb.x);
    y.y = gelu_exact((v.y - mu) * rstd * wv.y + bb.y);
    y.z = gelu_exact((v.z - mu) * rstd * wv.z + bb.z);
    y.w = gelu_exact((v.w - mu) * rstd * wv.w + bb.w);
    ((float4*)(Y + (size_t)row * Hh))[tid] = y;
}

// ---------------- GELU -> LayerNorm (one block per row) ----------------
__global__ void gelu_ln_kernel(const float* __restrict__ X, const float* __restrict__ w,
                               const float* __restrict__ bv, float* __restrict__ Y)
{
    __shared__ float red[2][8];
    const int row = blockIdx.x;
    const int tid = threadIdx.x;
    float4 v = ((const float4*)(X + (size_t)row * Hh))[tid];
    v.x = gelu_exact(v.x); v.y = gelu_exact(v.y);
    v.z = gelu_exact(v.z); v.w = gelu_exact(v.w);
    float s = v.x + v.y + v.z + v.w;
    float q = v.x*v.x + v.y*v.y + v.z*v.z + v.w*v.w;
    int lane = tid & 31, wid = tid >> 5;
#pragma unroll
    for (int o = 16; o; o >>= 1) {
        s += __shfl_xor_sync(0xffffffffu, s, o);
        q += __shfl_xor_sync(0xffffffffu, q, o);
    }
    if (lane == 0) { red[0][wid] = s; red[1][wid] = q; }
    __syncthreads();
    if (wid == 0) {
        s = (lane < 8) ? red[0][lane] : 0.f;
        q = (lane < 8) ? red[1][lane] : 0.f;
#pragma unroll
        for (int o = 4; o; o >>= 1) {
            s += __shfl_xor_sync(0xffffffffu, s, o);
            q += __shfl_xor_sync(0xffffffffu, q, o);
        }
        if (lane == 0) { red[0][0] = s; red[1][0] = q; }
    }
    __syncthreads();
    float mu  = red[0][0] * (1.f / Hh);
    float var = red[1][0] * (1.f / Hh) - mu * mu;
    float rstd = rsqrtf(var + 1e-5f);
    float4 wv = ((const float4*)w)[tid];
    float4 bb = ((const float4*)bv)[tid];
    float4 y;
    y.x = (v.x - mu) * rstd * wv.x + bb.x;
    y.y = (v.y - mu) * rstd * wv.y + bb.y;
    y.z = (v.z - mu) * rstd * wv.z + bb.z;
    y.w = (v.w - mu) * rstd * wv.w + bb.w;
    ((float4*)(Y + (size_t)row * Hh))[tid] = y;
}

// ---------------- driver ----------------
extern "C" void kernel_launch(void* const* d_in, const int* in_sizes, int n_in,
                              void* d_out, int out_size)
{
    const float* bone  = (const float*)d_in[0];
    const float* W_ih0 = (const float*)d_in[1];
    const float* W_hh0 = (const float*)d_in[2];
    const float* b_ih0 = (const float*)d_in[3];
    const float* b_hh0 = (const float*)d_in[4];
    const float* W_ih1 = (const float*)d_in[5];
    const float* W_hh1 = (const float*)d_in[6];
    const float* b_ih1 = (const float*)d_in[7];
    const float* b_hh1 = (const float*)d_in[8];
    const float* ln1w  = (const float*)d_in[9];
    const float* ln1b  = (const float*)d_in[10];
    const float* linw  = (const float*)d_in[11];
    const float* linb  = (const float*)d_in[12];
    const float* ln2w  = (const float*)d_in[13];
    const float* ln2b  = (const float*)d_in[14];
    float* out = (float*)d_out;

    float *xg = nullptr, *hseq = nullptr, *wf0 = nullptr, *wf1 = nullptr;
    cudaGetSymbolAddress((void**)&xg, g_xg);
    cudaGetSymbolAddress((void**)&hseq, g_hseq);
    cudaGetSymbolAddress((void**)&wf0, g_wf0);
    cudaGetSymbolAddress((void**)&wf1, g_wf1);
    float* act = xg;
    float* lin = xg + (size_t)BT * Hh;

    cudaFuncSetAttribute(lstm_scan, cudaFuncAttributeMaxDynamicSharedMemorySize, SCAN_SMEM);

    dim3 gemm_g4(G4/128, BT/128);
    dim3 gemm_h(Hh/128, BT/128);

    // weight fragment prep (runs per call; ~tens of µs)
    prep_whh<<<4096, 256>>>(W_hh0, wf0);
    prep_whh<<<4096, 256>>>(W_hh1, wf1);

    // layer 0
    gemm_nt_bias<<<gemm_g4, 256>>>(bone, W_ih0, b_ih0, b_hh0, xg, BT, G4, Dd);
    reset_scan_state<<<64, 256>>>();
    lstm_scan<<<NCTA, 256, SCAN_SMEM>>>(wf0, xg, hseq);

    // layer 1
    gemm_nt_bias<<<gemm_g4, 256>>>(hseq, W_ih1, b_ih1, b_hh1, xg, BT, G4, Hh);
    reset_scan_state<<<64, 256>>>();
    lstm_scan<<<NCTA, 256, SCAN_SMEM>>>(wf1, xg, hseq);

    // post: LN -> GELU -> Linear -> GELU -> LN
    ln_gelu_kernel<<<BT, 256>>>(hseq, ln1w, ln1b, act);
    gemm_nt_bias<<<gemm_h, 256>>>(act, linw, linb, nullptr, lin, BT, Hh, Hh);
    gelu_ln_kernel<<<BT, 256>>>(lin, ln2w, ln2b, out);
}

// round 4
// speedup vs baseline: 2.7177x; 1.1967x over previous
#include <cuda_runtime.h>
#include <math.h>
#include <stdint.h>
#include <stddef.h>

#define Bb 32
#define Tt 512
#define Dd 256
#define Hh 1024
#define G4 4096
#define BT (Bb*Tt)          // 16384
#define NCTA 128

// ---------------- scratch (device globals; no allocation allowed) ----------------
__device__ float g_xg[(size_t)BT * G4];     // 256 MB: gate preactivations / reuse
__device__ float g_hseq[(size_t)BT * Hh];   // 64 MB: per-layer output sequence
__device__ float g_hfrag[2 * Hh * Bb];      // h double buffer, tf32 bits, B-fragment layout
__device__ float g_wf0[(size_t)G4 * Hh];    // W_hh0 in A-fragment layout (tf32 bits)
__device__ float g_wf1[(size_t)G4 * Hh];    // W_hh1 likewise
__device__ unsigned int g_cnt;              // grid barrier counter

#define PART_STRIDE 1056    // 32 rows * 33 (padded)
#define SCAN_SMEM ((32*1024 + 8*PART_STRIDE + 1024) * 4)

// ---------------- helpers ----------------
__device__ __forceinline__ float sigm(float x) { return 1.f / (1.f + expf(-x)); }
__device__ __forceinline__ float gelu_exact(float x) {
    return 0.5f * x * (1.f + erff(x * 0.70710678118654752440f));
}
__device__ __forceinline__ unsigned tf32_rna(float x) {
    unsigned r; asm("cvt.rna.tf32.f32 %0, %1;" : "=r"(r) : "f"(x)); return r;
}
__device__ __forceinline__ void mma_tf32(float c[4], const unsigned a[4],
                                         unsigned b0, unsigned b1) {
    asm("mma.sync.aligned.m16n8k8.row.col.f32.tf32.tf32.f32 "
        "{%0,%1,%2,%3},{%4,%5,%6,%7},{%8,%9},{%0,%1,%2,%3};"
        : "+f"(c[0]), "+f"(c[1]), "+f"(c[2]), "+f"(c[3])
        : "r"(a[0]), "r"(a[1]), "r"(a[2]), "r"(a[3]), "r"(b0), "r"(b1));
}

// ---------------- prep: W_hh[4H][H] -> per-CTA mma A-fragment layout ----------------
__global__ void prep_whh(const float* __restrict__ W, float* __restrict__ out) {
    int idx = blockIdx.x * 256 + threadIdx.x;
    int lane = idx & 31;
    int mt   = (idx >> 5) & 1;
    int kk   = (idx >> 6) & 127;
    int c    = idx >> 13;
    float tmp[4];
#pragma unroll
    for (int j = 0; j < 4; j++) {
        int rl = mt*16 + (lane >> 2) + ((j & 1) << 3);
        int k  = kk*8 + (lane & 3) + ((j >> 1) << 2);
        int R  = (rl >> 3) * 1024 + c*8 + (rl & 7);
        tmp[j] = __uint_as_float(tf32_rna(W[(size_t)R * Hh + k]));
    }
    ((float4*)out)[idx] = make_float4(tmp[0], tmp[1], tmp[2], tmp[3]);
}

// ---------------- reset ----------------
__global__ void reset_scan_state() {
    int i = blockIdx.x * blockDim.x + threadIdx.x;
    if (i == 0) g_cnt = 0u;
    for (int j = i; j < 2 * Hh * Bb; j += gridDim.x * blockDim.x) g_hfrag[j] = 0.f;
}

// ---------------- tf32 tensor-core GEMM: C[m][n] = sum_k A[m][k]*Bw[n][k] + bias ----------------
// M,N multiples of 128; K multiple of 16. 256 threads, block tile 128x128,
// warp tile 64x32 (2x4 warps), K-chunk 16, double-buffered smem.
#define GPAD 130
__global__ void __launch_bounds__(256) gemm_tf32_nt_bias(
    const float* __restrict__ A, const float* __restrict__ Bw,
    const float* __restrict__ b1, const float* __restrict__ b2,
    float* __restrict__ C, int M, int N, int K)
{
    __shared__ float As[2][16*GPAD];
    __shared__ float Bs[2][16*GPAD];

    const int tid  = threadIdx.x;
    const int lane = tid & 31;
    const int wid  = tid >> 5;
    const int bm   = blockIdx.y << 7;
    const int bn   = blockIdx.x << 7;
    const int wm   = (wid >> 2) << 6;     // 0 / 64
    const int wn   = (wid & 3) << 5;      // 0/32/64/96
    const int lr   = lane >> 2;
    const int lc   = lane & 3;

    const int mrow  = tid >> 1;           // 0..127
    const int khalf = (tid & 1) << 3;     // 0 / 8

    const float* Ap = A + (size_t)(bm + mrow) * K + khalf;
    const float* Bp = Bw + (size_t)(bn + mrow) * K + khalf;

    float acc[4][4][4];
#pragma unroll
    for (int mt = 0; mt < 4; mt++)
#pragma unroll
        for (int nt = 0; nt < 4; nt++)
#pragma unroll
            for (int j = 0; j < 4; j++) acc[mt][nt][j] = 0.f;

    const int NC = K >> 4;
    float4 ra0, ra1, rb0, rb1;

    // prologue: chunk 0
    ra0 = *(const float4*)(Ap + 0);  ra1 = *(const float4*)(Ap + 4);
    rb0 = *(const float4*)(Bp + 0);  rb1 = *(const float4*)(Bp + 4);
    {
        float* as = &As[0][0]; float* bs = &Bs[0][0];
        as[(khalf+0)*GPAD + mrow] = __uint_as_float(tf32_rna(ra0.x));
        as[(khalf+1)*GPAD + mrow] = __uint_as_float(tf32_rna(ra0.y));
        as[(khalf+2)*GPAD + mrow] = __uint_as_float(tf32_rna(ra0.z));
        as[(khalf+3)*GPAD + mrow] = __uint_as_float(tf32_rna(ra0.w));
        as[(khalf+4)*GPAD + mrow] = __uint_as_float(tf32_rna(ra1.x));
        as[(khalf+5)*GPAD + mrow] = __uint_as_float(tf32_rna(ra1.y));
        as[(khalf+6)*GPAD + mrow] = __uint_as_float(tf32_rna(ra1.z));
        as[(khalf+7)*GPAD + mrow] = __uint_as_float(tf32_rna(ra1.w));
        bs[(khalf+0)*GPAD + mrow] = __uint_as_float(tf32_rna(rb0.x));
        bs[(khalf+1)*GPAD + mrow] = __uint_as_float(tf32_rna(rb0.y));
        bs[(khalf+2)*GPAD + mrow] = __uint_as_float(tf32_rna(rb0.z));
        bs[(khalf+3)*GPAD + mrow] = __uint_as_float(tf32_rna(rb0.w));
        bs[(khalf+4)*GPAD + mrow] = __uint_as_float(tf32_rna(rb1.x));
        bs[(khalf+5)*GPAD + mrow] = __uint_as_float(tf32_rna(rb1.y));
        bs[(khalf+6)*GPAD + mrow] = __uint_as_float(tf32_rna(rb1.z));
        bs[(khalf+7)*GPAD + mrow] = __uint_as_float(tf32_rna(rb1.w));
    }
    __syncthreads();

    for (int c = 0; c < NC; c++) {
        const int p = c & 1;
        if (c + 1 < NC) {
            const float* Apn = Ap + (size_t)(c + 1) * 16;
            const float* Bpn = Bp + (size_t)(c + 1) * 16;
            ra0 = *(const float4*)(Apn + 0);  ra1 = *(const float4*)(Apn + 4);
            rb0 = *(const float4*)(Bpn + 0);  rb1 = *(const float4*)(Bpn + 4);
        }

        const float* as = &As[p][0];
        const float* bs = &Bs[p][0];
#pragma unroll
        for (int ks = 0; ks < 2; ks++) {
            const int kb = ks << 3;
            unsigned Af[4][4];
#pragma unroll
            for (int mt = 0; mt < 4; mt++) {
                int base = (kb + lc)*GPAD + wm + mt*16 + lr;
                Af[mt][0] = __float_as_uint(as[base]);
                Af[mt][1] = __float_as_uint(as[base + 8]);
                Af[mt][2] = __float_as_uint(as[base + 4*GPAD]);
                Af[mt][3] = __float_as_uint(as[base + 4*GPAD + 8]);
            }
            unsigned Bf[4][2];
#pragma unroll
            for (int nt = 0; nt < 4; nt++) {
                int base = (kb + lc)*GPAD + wn + nt*8 + lr;
                Bf[nt][0] = __float_as_uint(bs[base]);
                Bf[nt][1] = __float_as_uint(bs[base + 4*GPAD]);
            }
#pragma unroll
            for (int mt = 0; mt < 4; mt++)
#pragma unroll
                for (int nt = 0; nt < 4; nt++)
                    mma_tf32(acc[mt][nt], Af[mt], Bf[nt][0], Bf[nt][1]);
        }

        if (c + 1 < NC) {
            float* asn = &As[1 - p][0]; float* bsn = &Bs[1 - p][0];
            asn[(khalf+0)*GPAD + mrow] = __uint_as_float(tf32_rna(ra0.x));
            asn[(khalf+1)*GPAD + mrow] = __uint_as_float(tf32_rna(ra0.y));
            asn[(khalf+2)*GPAD + mrow] = __uint_as_float(tf32_rna(ra0.z));
            asn[(khalf+3)*GPAD + mrow] = __uint_as_float(tf32_rna(ra0.w));
            asn[(khalf+4)*GPAD + mrow] = __uint_as_float(tf32_rna(ra1.x));
            asn[(khalf+5)*GPAD + mrow] = __uint_as_float(tf32_rna(ra1.y));
            asn[(khalf+6)*GPAD + mrow] = __uint_as_float(tf32_rna(ra1.z));
            asn[(khalf+7)*GPAD + mrow] = __uint_as_float(tf32_rna(ra1.w));
            bsn[(khalf+0)*GPAD + mrow] = __uint_as_float(tf32_rna(rb0.x));
            bsn[(khalf+1)*GPAD + mrow] = __uint_as_float(tf32_rna(rb0.y));
            bsn[(khalf+2)*GPAD + mrow] = __uint_as_float(tf32_rna(rb0.z));
            bsn[(khalf+3)*GPAD + mrow] = __uint_as_float(tf32_rna(rb0.w));
            bsn[(khalf+4)*GPAD + mrow] = __uint_as_float(tf32_rna(rb1.x));
            bsn[(khalf+5)*GPAD + mrow] = __uint_as_float(tf32_rna(rb1.y));
            bsn[(khalf+6)*GPAD + mrow] = __uint_as_float(tf32_rna(rb1.z));
            bsn[(khalf+7)*GPAD + mrow] = __uint_as_float(tf32_rna(rb1.w));
            __syncthreads();
        }
    }

    // epilogue: bias + store (float2 per c-frag row pair)
#pragma unroll
    for (int nt = 0; nt < 4; nt++) {
        int col = bn + wn + nt*8 + lc*2;
        float bb0 = b1[col]     + (b2 ? b2[col]     : 0.f);
        float bb1 = b1[col + 1] + (b2 ? b2[col + 1] : 0.f);
#pragma unroll
        for (int mt = 0; mt < 4; mt++) {
            int row = bm + wm + mt*16 + lr;
            float2 v0 = make_float2(acc[mt][nt][0] + bb0, acc[mt][nt][1] + bb1);
            float2 v1 = make_float2(acc[mt][nt][2] + bb0, acc[mt][nt][3] + bb1);
            *(float2*)(C + (size_t)row * N + col)       = v0;
            *(float2*)(C + (size_t)(row + 8) * N + col) = v1;
        }
    }
}

// ---------------- persistent LSTM scan (tf32 tensor-core recurrence) ----------------
__global__ void __launch_bounds__(256, 1) lstm_scan(
    const float* __restrict__ wf,
    const float* __restrict__ xg,
    float* __restrict__ hseq)
{
    extern __shared__ float smem[];
    float* sW   = smem;
    float* part = smem + 32768;
    float* sXG  = part + 8*PART_STRIDE;

    const int tid  = threadIdx.x;
    const int lane = tid & 31;
    const int kg   = tid >> 5;
    const int u0   = blockIdx.x * 8;

    {
        const float4* wsrc = (const float4*)(wf + (size_t)blockIdx.x * 32768);
        float4* wdst = (float4*)sW;
        for (int i = tid; i < 8192; i += 256) wdst[i] = wsrc[i];
    }

    const int pb = tid >> 3;
    const int pg = (tid >> 1) & 3;
    const int ph = (tid & 1) << 2;
    const float* xg_base = xg + (size_t)pb * Tt * G4 + pg*1024 + u0 + ph;
    float4 px = *(const float4*)xg_base;

    const int uu = tid >> 5;
    const int b  = lane;
    float c_state = 0.f;
    unsigned bar = 0;
    __syncthreads();

    for (int t = 0; t < Tt; t++) {
        {
            float* d = sXG + pb*32 + pg*8 + ph;
            d[0] = px.x; d[1] = px.y; d[2] = px.z; d[3] = px.w;
            int tn = (t + 1 < Tt) ? (t + 1) : t;
            px = *(const float4*)(xg_base + (size_t)tn * G4);
        }

        const int rp = t & 1;
        const float* hb = g_hfrag + rp * (Hh * Bb);

        float acc[2][4][4];
#pragma unroll
        for (int mt = 0; mt < 2; mt++)
#pragma unroll
            for (int nt = 0; nt < 4; nt++)
#pragma unroll
                for (int j = 0; j < 4; j++) acc[mt][nt][j] = 0.f;

#pragma unroll 4
        for (int ks = 0; ks < 16; ks++) {
            const int kk = kg*16 + ks;
            float4 wa0 = ((const float4*)sW)[(kk*2+0)*32 + lane];
            float4 wa1 = ((const float4*)sW)[(kk*2+1)*32 + lane];
            unsigned A0[4] = {__float_as_uint(wa0.x), __float_as_uint(wa0.y),
                              __float_as_uint(wa0.z), __float_as_uint(wa0.w)};
            unsigned A1[4] = {__float_as_uint(wa1.x), __float_as_uint(wa1.y),
                              __float_as_uint(wa1.z), __float_as_uint(wa1.w)};
            float2 bv[4];
#pragma unroll
            for (int nt = 0; nt < 4; nt++)
                bv[nt] = __ldcg((const float2*)(hb + ((size_t)(kk*4+nt)*32 + lane)*2));
#pragma unroll
            for (int nt = 0; nt < 4; nt++) {
                unsigned b0 = __float_as_uint(bv[nt].x);
                unsigned b1 = __float_as_uint(bv[nt].y);
                mma_tf32(acc[0][nt], A0, b0, b1);
                mma_tf32(acc[1][nt], A1, b0, b1);
            }
        }

#pragma unroll
        for (int mt = 0; mt < 2; mt++)
#pragma unroll
            for (int nt = 0; nt < 4; nt++)
#pragma unroll
                for (int j = 0; j < 4; j++) {
                    int r = mt*16 + (lane >> 2) + ((j >> 1) << 3);
                    int n = nt*8 + ((lane & 3) << 1) + (j & 1);
                    part[kg*PART_STRIDE + r*33 + n] = acc[mt][nt][j];
                }
        __syncthreads();

        float ga[4];
#pragma unroll
        for (int g = 0; g < 4; g++) {
            int r = g*8 + uu;
            float s = 0.f;
#pragma unroll
            for (int q = 0; q < 8; q++) s += part[q*PART_STRIDE + r*33 + b];
            ga[g] = s + sXG[b*32 + g*8 + uu];
        }
        float ig = sigm(ga[0]);
        float fg = sigm(ga[1]);
        float gg = tanhf(ga[2]);
        float og = sigm(ga[3]);
        c_state = fg * c_state + ig * gg;
        float hval = og * tanhf(c_state);

        int u = u0 + uu;
        int pos = ((u >> 3)*4 + (b >> 3))*64 + ((b & 7)*4 + (u & 3))*2 + ((u >> 2) & 1);
        __stcg(g_hfrag + (1 - rp)*(Hh*Bb) + pos, __uint_as_float(tf32_rna(hval)));
        hseq[((size_t)b * Tt + t) * Hh + u] = hval;

        __syncthreads();
        if (tid == 0) {
            __threadfence();
            atomicAdd(&g_cnt, 1u);
            bar += NCTA;
            while (*((volatile unsigned int*)&g_cnt) < bar) { }
            __threadfence();
        }
        __syncthreads();
    }
}

// ---------------- LayerNorm -> GELU ----------------
__global__ void ln_gelu_kernel(const float* __restrict__ X, const float* __restrict__ w,
                               const float* __restrict__ bv, float* __restrict__ Y)
{
    __shared__ float red[2][8];
    const int row = blockIdx.x;
    const int tid = threadIdx.x;
    float4 v = ((const float4*)(X + (size_t)row * Hh))[tid];
    float s = v.x + v.y + v.z + v.w;
    float q = v.x*v.x + v.y*v.y + v.z*v.z + v.w*v.w;
    int lane = tid & 31, wid = tid >> 5;
#pragma unroll
    for (int o = 16; o; o >>= 1) {
        s += __shfl_xor_sync(0xffffffffu, s, o);
        q += __shfl_xor_sync(0xffffffffu, q, o);
    }
    if (lane == 0) { red[0][wid] = s; red[1][wid] = q; }
    __syncthreads();
    if (wid == 0) {
        s = (lane < 8) ? red[0][lane] : 0.f;
        q = (lane < 8) ? red[1][lane] : 0.f;
#pragma unroll
        for (int o = 4; o; o >>= 1) {
            s += __shfl_xor_sync(0xffffffffu, s, o);
            q += __shfl_xor_sync(0xffffffffu, q, o);
        }
        if (lane == 0) { red[0][0] = s; red[1][0] = q; }
    }
    __syncthreads();
    float mu  = red[0][0] * (1.f / Hh);
    float var = red[1][0] * (1.f / Hh) - mu * mu;
    float rstd = rsqrtf(var + 1e-5f);
    float4 wv = ((const float4*)w)[tid];
    float4 bb = ((const float4*)bv)[tid];
    float4 y;
    y.x = gelu_exact((v.x - mu) * rstd * wv.x + bb.x);
    y.y = gelu_exact((v.y - mu) * rstd * wv.y + bb.y);
    y.z = gelu_exact((v.z - mu) * rstd * wv.z + bb.z);
    y.w = gelu_exact((v.w - mu) * rstd * wv.w + bb.w);
    ((float4*)(Y + (size_t)row * Hh))[tid] = y;
}

// ---------------- GELU -> LayerNorm ----------------
__global__ void gelu_ln_kernel(const float* __restrict__ X, const float* __restrict__ w,
                               const float* __restrict__ bv, float* __restrict__ Y)
{
    __shared__ float red[2][8];
    const int row = blockIdx.x;
    const int tid = threadIdx.x;
    float4 v = ((const float4*)(X + (size_t)row * Hh))[tid];
    v.x = gelu_exact(v.x); v.y = gelu_exact(v.y);
    v.z = gelu_exact(v.z); v.w = gelu_exact(v.w);
    float s = v.x + v.y + v.z + v.w;
    float q = v.x*v.x + v.y*v.y + v.z*v.z + v.w*v.w;
    int lane = tid & 31, wid = tid >> 5;
#pragma unroll
    for (int o = 16; o; o >>= 1) {
        s += __shfl_xor_sync(0xffffffffu, s, o);
        q += __shfl_xor_sync(0xffffffffu, q, o);
    }
    if (lane == 0) { red[0][wid] = s; red[1][wid] = q; }
    __syncthreads();
    if (wid == 0) {
        s = (lane < 8) ? red[0][lane] : 0.f;
        q = (lane < 8) ? red[1][lane] : 0.f;
#pragma unroll
        for (int o = 4; o; o >>= 1) {
            s += __shfl_xor_sync(0xffffffffu, s, o);
            q += __shfl_xor_sync(0xffffffffu, q, o);
        }
        if (lane == 0) { red[0][0] = s; red[1][0] = q; }
    }
    __syncthreads();
    float mu  = red[0][0] * (1.f / Hh);
    float var = red[1][0] * (1.f / Hh) - mu * mu;
    float rstd = rsqrtf(var + 1e-5f);
    float4 wv = ((const float4*)w)[tid];
    float4 bb = ((const float4*)bv)[tid];
    float4 y;
    y.x = (v.x - mu) * rstd * wv.x + bb.x;
    y.y = (v.y - mu) * rstd * wv.y + bb.y;
    y.z = (v.z - mu) * rstd * wv.z + bb.z;
    y.w = (v.w - mu) * rstd * wv.w + bb.w;
    ((float4*)(Y + (size_t)row * Hh))[tid] = y;
}

// ---------------- driver ----------------
extern "C" void kernel_launch(void* const* d_in, const int* in_sizes, int n_in,
                              void* d_out, int out_size)
{
    const float* bone  = (const float*)d_in[0];
    const float* W_ih0 = (const float*)d_in[1];
    const float* W_hh0 = (const float*)d_in[2];
    const float* b_ih0 = (const float*)d_in[3];
    const float* b_hh0 = (const float*)d_in[4];
    const float* W_ih1 = (const float*)d_in[5];
    const float* W_hh1 = (const float*)d_in[6];
    const float* b_ih1 = (const float*)d_in[7];
    const float* b_hh1 = (const float*)d_in[8];
    const float* ln1w  = (const float*)d_in[9];
    const float* ln1b  = (const float*)d_in[10];
    const float* linw  = (const float*)d_in[11];
    const float* linb  = (const float*)d_in[12];
    const float* ln2w  = (const float*)d_in[13];
    const float* ln2b  = (const float*)d_in[14];
    float* out = (float*)d_out;

    float *xg = nullptr, *hseq = nullptr, *wf0 = nullptr, *wf1 = nullptr;
    cudaGetSymbolAddress((void**)&xg, g_xg);
    cudaGetSymbolAddress((void**)&hseq, g_hseq);
    cudaGetSymbolAddress((void**)&wf0, g_wf0);
    cudaGetSymbolAddress((void**)&wf1, g_wf1);
    float* act = xg;
    float* lin = xg + (size_t)BT * Hh;

    cudaFuncSetAttribute(lstm_scan, cudaFuncAttributeMaxDynamicSharedMemorySize, SCAN_SMEM);

    dim3 gemm_g4(G4/128, BT/128);
    dim3 gemm_h(Hh/128, BT/128);

    prep_whh<<<4096, 256>>>(W_hh0, wf0);
    prep_whh<<<4096, 256>>>(W_hh1, wf1);

    // layer 0
    gemm_tf32_nt_bias<<<gemm_g4, 256>>>(bone, W_ih0, b_ih0, b_hh0, xg, BT, G4, Dd);
    reset_scan_state<<<64, 256>>>();
    lstm_scan<<<NCTA, 256, SCAN_SMEM>>>(wf0, xg, hseq);

    // layer 1
    gemm_tf32_nt_bias<<<gemm_g4, 256>>>(hseq, W_ih1, b_ih1, b_hh1, xg, BT, G4, Hh);
    reset_scan_state<<<64, 256>>>();
    lstm_scan<<<NCTA, 256, SCAN_SMEM>>>(wf1, xg, hseq);

    // post: LN -> GELU -> Linear -> GELU -> LN
    ln_gelu_kernel<<<BT, 256>>>(hseq, ln1w, ln1b, act);
    gemm_tf32_nt_bias<<<gemm_h, 256>>>(act, linw, linb, nullptr, lin, BT, Hh, Hh);
    gelu_ln_kernel<<<BT, 256>>>(lin, ln2w, ln2b, out);
}

// round 5
// speedup vs baseline: 3.2950x; 1.2124x over previous
#include <cuda_runtime.h>
#include <math.h>
#include <stdint.h>
#include <stddef.h>

#define Bb 32
#define Tt 512
#define Dd 256
#define Hh 1024
#define G4 4096
#define BT (Bb*Tt)          // 16384
#define NCTA 128

// ---------------- scratch (device globals; no allocation allowed) ----------------
__device__ float g_xg[(size_t)BT * G4];     // 256 MB
__device__ float g_hseq[(size_t)BT * Hh];   // 64 MB
__device__ float g_hfrag[2 * Hh * Bb];      // h double buffer (tf32 bits, B-frag layout)
__device__ float g_wf0[(size_t)G4 * Hh];    // W_hh0 A-fragment layout (tf32 bits)
__device__ float g_wf1[(size_t)G4 * Hh];
__device__ unsigned int g_cnt;

#define PART_STRIDE 1056                    // 32 rows * 33
#define SCAN_SMEM ((16*PART_STRIDE + 1024 + 8*33 + 32) * 4)

// ---------------- helpers ----------------
__device__ __forceinline__ float sigm(float x) { return 1.f / (1.f + expf(-x)); }
__device__ __forceinline__ float gelu_exact(float x) {
    return 0.5f * x * (1.f + erff(x * 0.70710678118654752440f));
}
__device__ __forceinline__ unsigned tf32_rna(float x) {
    unsigned r; asm("cvt.rna.tf32.f32 %0, %1;" : "=r"(r) : "f"(x)); return r;
}
__device__ __forceinline__ float tf32f(float x) { return __uint_as_float(tf32_rna(x)); }
__device__ __forceinline__ void mma_tf32(float c[4], const unsigned a[4],
                                         unsigned b0, unsigned b1) {
    asm("mma.sync.aligned.m16n8k8.row.col.f32.tf32.tf32.f32 "
        "{%0,%1,%2,%3},{%4,%5,%6,%7},{%8,%9},{%0,%1,%2,%3};"
        : "+f"(c[0]), "+f"(c[1]), "+f"(c[2]), "+f"(c[3])
        : "r"(a[0]), "r"(a[1]), "r"(a[2]), "r"(a[3]), "r"(b0), "r"(b1));
}

// ---------------- prep: W_hh[4H][H] -> per-CTA mma A-fragment layout ----------------
__global__ void prep_whh(const float* __restrict__ W, float* __restrict__ out) {
    int idx = blockIdx.x * 256 + threadIdx.x;
    int lane = idx & 31;
    int mt   = (idx >> 5) & 1;
    int kk   = (idx >> 6) & 127;
    int c    = idx >> 13;
    float tmp[4];
#pragma unroll
    for (int j = 0; j < 4; j++) {
        int rl = mt*16 + (lane >> 2) + ((j & 1) << 3);
        int k  = kk*8 + (lane & 3) + ((j >> 1) << 2);
        int R  = (rl >> 3) * 1024 + c*8 + (rl & 7);
        tmp[j] = __uint_as_float(tf32_rna(W[(size_t)R * Hh + k]));
    }
    ((float4*)out)[idx] = make_float4(tmp[0], tmp[1], tmp[2], tmp[3]);
}

// ---------------- reset ----------------
__global__ void reset_scan_state() {
    int i = blockIdx.x * blockDim.x + threadIdx.x;
    if (i == 0) g_cnt = 0u;
    for (int j = i; j < 2 * Hh * Bb; j += gridDim.x * blockDim.x) g_hfrag[j] = 0.f;
}

// ---------------- tf32 GEMM, fragment-native smem layout ----------------
// C[m][n] = sum_k A[m][k]*Bw[n][k] + b1[n] (+b2[n]).  128x128 tile, 256 thr,
// warp tile 64x32 (2x4), K-chunk 16, double buffer.  Smem layout [j][lane]:
//   A slot(blk = kk8*8 + mt16, j, lane) = A[row = mt16*16 + (j&1)*8 + lane>>2]
//                                          [k = kk8*8 + (j>>1)*4 + (lane&3)]
//   B slot(blk = kk8*16 + nb8, j, lane) = B[n = nb8*8 + lane>>2][k = kk8*8 + j*4 + (lane&3)]
__global__ void __launch_bounds__(256) gemm_tf32_nt_bias(
    const float* __restrict__ A, const float* __restrict__ Bw,
    const float* __restrict__ b1, const float* __restrict__ b2,
    float* __restrict__ C, int M, int N, int K)
{
    __shared__ float As[2][2048];
    __shared__ float Bs[2][2048];

    const int tid  = threadIdx.x;
    const int lane = tid & 31;
    const int wid  = tid >> 5;
    const int bm   = blockIdx.y << 7;
    const int bn   = blockIdx.x << 7;
    const int wm   = (wid >> 2) << 6;
    const int wn   = (wid & 3) << 5;
    const int lr   = lane >> 2;
    const int lc   = lane & 3;

    const int mrow = tid >> 1;            // 0..127
    const int kk8  = tid & 1;             // which k-octet this thread loads
    const int khalf = kk8 << 3;

    // precomputed scatter bases
    const int a_off = (kk8*8 + (mrow >> 4))*128 + ((mrow >> 3) & 1)*32 + (mrow & 7)*4;
    const int b_off = (kk8*16 + (mrow >> 3))*64 + (mrow & 7)*4;

    const float* Ap = A + (size_t)(bm + mrow) * K + khalf;
    const float* Bp = Bw + (size_t)(bn + mrow) * K + khalf;

    float acc[4][4][4];
#pragma unroll
    for (int mt = 0; mt < 4; mt++)
#pragma unroll
        for (int nt = 0; nt < 4; nt++)
#pragma unroll
            for (int j = 0; j < 4; j++) acc[mt][nt][j] = 0.f;

    const int NC = K >> 4;
    float4 ra0, ra1, rb0, rb1;

    // prologue
    ra0 = *(const float4*)(Ap + 0);  ra1 = *(const float4*)(Ap + 4);
    rb0 = *(const float4*)(Bp + 0);  rb1 = *(const float4*)(Bp + 4);
    {
        float* as = &As[0][0]; float* bs = &Bs[0][0];
        *(float4*)(as + a_off)      = make_float4(tf32f(ra0.x), tf32f(ra0.y), tf32f(ra0.z), tf32f(ra0.w));
        *(float4*)(as + a_off + 64) = make_float4(tf32f(ra1.x), tf32f(ra1.y), tf32f(ra1.z), tf32f(ra1.w));
        *(float4*)(bs + b_off)      = make_float4(tf32f(rb0.x), tf32f(rb0.y), tf32f(rb0.z), tf32f(rb0.w));
        *(float4*)(bs + b_off + 32) = make_float4(tf32f(rb1.x), tf32f(rb1.y), tf32f(rb1.z), tf32f(rb1.w));
    }
    __syncthreads();

    for (int c = 0; c < NC; c++) {
        const int p = c & 1;
        if (c + 1 < NC) {
            const float* Apn = Ap + (size_t)(c + 1) * 16;
            const float* Bpn = Bp + (size_t)(c + 1) * 16;
            ra0 = *(const float4*)(Apn + 0);  ra1 = *(const float4*)(Apn + 4);
            rb0 = *(const float4*)(Bpn + 0);  rb1 = *(const float4*)(Bpn + 4);
        }

        const float* as = &As[p][0];
        const float* bs = &Bs[p][0];
#pragma unroll
        for (int ks = 0; ks < 2; ks++) {
            unsigned Af[4][4];
#pragma unroll
            for (int mt = 0; mt < 4; mt++) {
                const float* ap = as + (ks*8 + (wm >> 4) + mt)*128 + lane;
                Af[mt][0] = __float_as_uint(ap[0]);
                Af[mt][1] = __float_as_uint(ap[32]);
                Af[mt][2] = __float_as_uint(ap[64]);
                Af[mt][3] = __float_as_uint(ap[96]);
            }
            unsigned Bf[4][2];
#pragma unroll
            for (int nt = 0; nt < 4; nt++) {
                const float* bp = bs + (ks*16 + (wn >> 3) + nt)*64 + lane;
                Bf[nt][0] = __float_as_uint(bp[0]);
                Bf[nt][1] = __float_as_uint(bp[32]);
            }
#pragma unroll
            for (int mt = 0; mt < 4; mt++)
#pragma unroll
                for (int nt = 0; nt < 4; nt++)
                    mma_tf32(acc[mt][nt], Af[mt], Bf[nt][0], Bf[nt][1]);
        }

        if (c + 1 < NC) {
            float* asn = &As[1 - p][0]; float* bsn = &Bs[1 - p][0];
            *(float4*)(asn + a_off)      = make_float4(tf32f(ra0.x), tf32f(ra0.y), tf32f(ra0.z), tf32f(ra0.w));
            *(float4*)(asn + a_off + 64) = make_float4(tf32f(ra1.x), tf32f(ra1.y), tf32f(ra1.z), tf32f(ra1.w));
            *(float4*)(bsn + b_off)      = make_float4(tf32f(rb0.x), tf32f(rb0.y), tf32f(rb0.z), tf32f(rb0.w));
            *(float4*)(bsn + b_off + 32) = make_float4(tf32f(rb1.x), tf32f(rb1.y), tf32f(rb1.z), tf32f(rb1.w));
            __syncthreads();
        }
    }

    // epilogue: bias + store
#pragma unroll
    for (int nt = 0; nt < 4; nt++) {
        int col = bn + wn + nt*8 + lc*2;
        float bb0 = b1[col]     + (b2 ? b2[col]     : 0.f);
        float bb1 = b1[col + 1] + (b2 ? b2[col + 1] : 0.f);
#pragma unroll
        for (int mt = 0; mt < 4; mt++) {
            int row = bm + wm + mt*16 + lr;
            float2 v0 = make_float2(acc[mt][nt][0] + bb0, acc[mt][nt][1] + bb1);
            float2 v1 = make_float2(acc[mt][nt][2] + bb0, acc[mt][nt][3] + bb1);
            *(float2*)(C + (size_t)row * N + col)       = v0;
            *(float2*)(C + (size_t)(row + 8) * N + col) = v1;
        }
    }
}

// ---------------- persistent LSTM scan: 512 threads, W in registers ----------------
// 128 CTAs x 512 threads (16 warps). CTA owns units [c*8, c*8+8) = 32 gate rows.
// Warp kg handles K-chunk [kg*64, kg*64+64) (8 k-octets), W frags in registers.
// h loads from L2 pipelined one octet ahead.
__global__ void __launch_bounds__(512, 1) lstm_scan(
    const float* __restrict__ wf,
    const float* __restrict__ xg,
    float* __restrict__ hseq)
{
    extern __shared__ float smem[];
    float* part = smem;                          // 16 * 1056
    float* sXG  = part + 16*PART_STRIDE;         // 1024: [b][gate][u]
    float* sHT  = sXG + 1024;                    // 8*33: h transpose staging

    const int tid  = threadIdx.x;
    const int lane = tid & 31;
    const int kg   = tid >> 5;                   // warp id = K-group 0..15
    const int u0   = blockIdx.x * 8;

    // W fragments -> registers: 8 octets x 8 regs
    unsigned wreg[8][8];
    {
        const float4* wsrc = (const float4*)(wf + (size_t)blockIdx.x * 32768);
#pragma unroll
        for (int ks = 0; ks < 8; ks++) {
            int kk = kg*8 + ks;
            float4 w0 = wsrc[(kk*2+0)*32 + lane];
            float4 w1 = wsrc[(kk*2+1)*32 + lane];
            wreg[ks][0] = __float_as_uint(w0.x); wreg[ks][1] = __float_as_uint(w0.y);
            wreg[ks][2] = __float_as_uint(w0.z); wreg[ks][3] = __float_as_uint(w0.w);
            wreg[ks][4] = __float_as_uint(w1.x); wreg[ks][5] = __float_as_uint(w1.y);
            wreg[ks][6] = __float_as_uint(w1.z); wreg[ks][7] = __float_as_uint(w1.w);
        }
    }

    // xg staging: thread -> (batch pb, gate pg, 2-unit slot ph2)
    const int pb  = tid >> 4;
    const int pg  = (tid >> 2) & 3;
    const int ph2 = tid & 3;
    const float* xg_base = xg + (size_t)pb * Tt * G4 + pg*1024 + u0 + ph2*2;
    float2 px = *(const float2*)xg_base;

    const int uu = tid >> 5;    // pointwise mapping (tid < 256)
    const int b  = lane;
    float c_state = 0.f;
    unsigned bar = 0;

    for (int t = 0; t < Tt; t++) {
        // stage xg, prefetch next
        {
            float* d = sXG + pb*32 + pg*8 + ph2*2;
            d[0] = px.x; d[1] = px.y;
            int tn = (t + 1 < Tt) ? (t + 1) : t;
            px = *(const float2*)(xg_base + (size_t)tn * G4);
        }

        const int rp = t & 1;
        const float2* hb2 = (const float2*)(g_hfrag + rp * (Hh * Bb));

        float acc[2][4][4];
#pragma unroll
        for (int mt = 0; mt < 2; mt++)
#pragma unroll
            for (int nt = 0; nt < 4; nt++)
#pragma unroll
                for (int j = 0; j < 4; j++) acc[mt][nt][j] = 0.f;

        float2 cur[4];
#pragma unroll
        for (int nt = 0; nt < 4; nt++)
            cur[nt] = __ldcg(hb2 + ((kg*8 + 0)*4 + nt)*32 + lane);

#pragma unroll
        for (int ks = 0; ks < 8; ks++) {
            float2 nxt[4];
            if (ks < 7) {
#pragma unroll
                for (int nt = 0; nt < 4; nt++)
                    nxt[nt] = __ldcg(hb2 + ((kg*8 + ks + 1)*4 + nt)*32 + lane);
            }
            unsigned A0[4] = {wreg[ks][0], wreg[ks][1], wreg[ks][2], wreg[ks][3]};
            unsigned A1[4] = {wreg[ks][4], wreg[ks][5], wreg[ks][6], wreg[ks][7]};
#pragma unroll
            for (int nt = 0; nt < 4; nt++) {
                unsigned b0 = __float_as_uint(cur[nt].x);
                unsigned b1 = __float_as_uint(cur[nt].y);
                mma_tf32(acc[0][nt], A0, b0, b1);
                mma_tf32(acc[1][nt], A1, b0, b1);
            }
            if (ks < 7) {
#pragma unroll
                for (int nt = 0; nt < 4; nt++) cur[nt] = nxt[nt];
            }
        }

        // scatter partials
#pragma unroll
        for (int mt = 0; mt < 2; mt++)
#pragma unroll
            for (int nt = 0; nt < 4; nt++)
#pragma unroll
                for (int j = 0; j < 4; j++) {
                    int r = mt*16 + (lane >> 2) + ((j >> 1) << 3);
                    int n = nt*8 + ((lane & 3) << 1) + (j & 1);
                    part[kg*PART_STRIDE + r*33 + n] = acc[mt][nt][j];
                }
        __syncthreads();

        if (tid < 256) {
            float ga[4];
#pragma unroll
            for (int g = 0; g < 4; g++) {
                int r = g*8 + uu;
                float s = 0.f;
#pragma unroll
                for (int q = 0; q < 16; q++) s += part[q*PART_STRIDE + r*33 + b];
                ga[g] = s + sXG[b*32 + g*8 + uu];
            }
            float ig = sigm(ga[0]);
            float fg = sigm(ga[1]);
            float gg = tanhf(ga[2]);
            float og = sigm(ga[3]);
            c_state = fg * c_state + ig * gg;
            float hval = og * tanhf(c_state);

            int u = u0 + uu;
            int pos = ((u >> 3)*4 + (b >> 3))*64 + ((b & 7)*4 + (u & 3))*2 + ((u >> 2) & 1);
            __stcg(g_hfrag + (1 - rp)*(Hh*Bb) + pos, __uint_as_float(tf32_rna(hval)));
            sHT[uu*33 + b] = hval;
        }
        __syncthreads();

        // coalesced hseq write (8 consecutive floats per batch row)
        if (tid < 256) {
            int b_ = tid >> 3, uo = tid & 7;
            hseq[((size_t)b_ * Tt + t) * Hh + u0 + uo] = sHT[uo*33 + b_];
        }

        // grid barrier
        if (tid == 0) {
            __threadfence();
            atomicAdd(&g_cnt, 1u);
            bar += NCTA;
            while (*((volatile unsigned int*)&g_cnt) < bar) { }
            __threadfence();
        }
        __syncthreads();
    }
}

// ---------------- LayerNorm -> GELU ----------------
__global__ void ln_gelu_kernel(const float* __restrict__ X, const float* __restrict__ w,
                               const float* __restrict__ bv, float* __restrict__ Y)
{
    __shared__ float red[2][8];
    const int row = blockIdx.x;
    const int tid = threadIdx.x;
    float4 v = ((const float4*)(X + (size_t)row * Hh))[tid];
    float s = v.x + v.y + v.z + v.w;
    float q = v.x*v.x + v.y*v.y + v.z*v.z + v.w*v.w;
    int lane = tid & 31, wid = tid >> 5;
#pragma unroll
    for (int o = 16; o; o >>= 1) {
        s += __shfl_xor_sync(0xffffffffu, s, o);
        q += __shfl_xor_sync(0xffffffffu, q, o);
    }
    if (lane == 0) { red[0][wid] = s; red[1][wid] = q; }
    __syncthreads();
    if (wid == 0) {
        s = (lane < 8) ? red[0][lane] : 0.f;
        q = (lane < 8) ? red[1][lane] : 0.f;
#pragma unroll
        for (int o = 4; o; o >>= 1) {
            s += __shfl_xor_sync(0xffffffffu, s, o);
            q += __shfl_xor_sync(0xffffffffu, q, o);
        }
        if (lane == 0) { red[0][0] = s; red[1][0] = q; }
    }
    __syncthreads();
    float mu  = red[0][0] * (1.f / Hh);
    float var = red[1][0] * (1.f / Hh) - mu * mu;
    float rstd = rsqrtf(var + 1e-5f);
    float4 wv = ((const float4*)w)[tid];
    float4 bb = ((const float4*)bv)[tid];
    float4 y;
    y.x = gelu_exact((v.x - mu) * rstd * wv.x + bb.x);
    y.y = gelu_exact((v.y - mu) * rstd * wv.y + bb.y);
    y.z = gelu_exact((v.z - mu) * rstd * wv.z + bb.z);
    y.w = gelu_exact((v.w - mu) * rstd * wv.w + bb.w);
    ((float4*)(Y + (size_t)row * Hh))[tid] = y;
}

// ---------------- GELU -> LayerNorm ----------------
__global__ void gelu_ln_kernel(const float* __restrict__ X, const float* __restrict__ w,
                               const float* __restrict__ bv, float* __restrict__ Y)
{
    __shared__ float red[2][8];
    const int row = blockIdx.x;
    const int tid = threadIdx.x;
    float4 v = ((const float4*)(X + (size_t)row * Hh))[tid];
    v.x = gelu_exact(v.x); v.y = gelu_exact(v.y);
    v.z = gelu_exact(v.z); v.w = gelu_exact(v.w);
    float s = v.x + v.y + v.z + v.w;
    float q = v.x*v.x + v.y*v.y + v.z*v.z + v.w*v.w;
    int lane = tid & 31, wid = tid >> 5;
#pragma unroll
    for (int o = 16; o; o >>= 1) {
        s += __shfl_xor_sync(0xffffffffu, s, o);
        q += __shfl_xor_sync(0xffffffffu, q, o);
    }
    if (lane == 0) { red[0][wid] = s; red[1][wid] = q; }
    __syncthreads();
    if (wid == 0) {
        s = (lane < 8) ? red[0][lane] : 0.f;
        q = (lane < 8) ? red[1][lane] : 0.f;
#pragma unroll
        for (int o = 4; o; o >>= 1) {
            s += __shfl_xor_sync(0xffffffffu, s, o);
            q += __shfl_xor_sync(0xffffffffu, q, o);
        }
        if (lane == 0) { red[0][0] = s; red[1][0] = q; }
    }
    __syncthreads();
    float mu  = red[0][0] * (1.f / Hh);
    float var = red[1][0] * (1.f / Hh) - mu * mu;
    float rstd = rsqrtf(var + 1e-5f);
    float4 wv = ((const float4*)w)[tid];
    float4 bb = ((const float4*)bv)[tid];
    float4 y;
    y.x = (v.x - mu) * rstd * wv.x + bb.x;
    y.y = (v.y - mu) * rstd * wv.y + bb.y;
    y.z = (v.z - mu) * rstd * wv.z + bb.z;
    y.w = (v.w - mu) * rstd * wv.w + bb.w;
    ((float4*)(Y + (size_t)row * Hh))[tid] = y;
}

// ---------------- driver ----------------
extern "C" void kernel_launch(void* const* d_in, const int* in_sizes, int n_in,
                              void* d_out, int out_size)
{
    const float* bone  = (const float*)d_in[0];
    const float* W_ih0 = (const float*)d_in[1];
    const float* W_hh0 = (const float*)d_in[2];
    const float* b_ih0 = (const float*)d_in[3];
    const float* b_hh0 = (const float*)d_in[4];
    const float* W_ih1 = (const float*)d_in[5];
    const float* W_hh1 = (const float*)d_in[6];
    const float* b_ih1 = (const float*)d_in[7];
    const float* b_hh1 = (const float*)d_in[8];
    const float* ln1w  = (const float*)d_in[9];
    const float* ln1b  = (const float*)d_in[10];
    const float* linw  = (const float*)d_in[11];
    const float* linb  = (const float*)d_in[12];
    const float* ln2w  = (const float*)d_in[13];
    const float* ln2b  = (const float*)d_in[14];
    float* out = (float*)d_out;

    float *xg = nullptr, *hseq = nullptr, *wf0 = nullptr, *wf1 = nullptr;
    cudaGetSymbolAddress((void**)&xg, g_xg);
    cudaGetSymbolAddress((void**)&hseq, g_hseq);
    cudaGetSymbolAddress((void**)&wf0, g_wf0);
    cudaGetSymbolAddress((void**)&wf1, g_wf1);
    float* act = xg;
    float* lin = xg + (size_t)BT * Hh;

    cudaFuncSetAttribute(lstm_scan, cudaFuncAttributeMaxDynamicSharedMemorySize, SCAN_SMEM);

    dim3 gemm_g4(G4/128, BT/128);
    dim3 gemm_h(Hh/128, BT/128);

    prep_whh<<<4096, 256>>>(W_hh0, wf0);
    prep_whh<<<4096, 256>>>(W_hh1, wf1);

    // layer 0
    gemm_tf32_nt_bias<<<gemm_g4, 256>>>(bone, W_ih0, b_ih0, b_hh0, xg, BT, G4, Dd);
    reset_scan_state<<<64, 256>>>();
    lstm_scan<<<NCTA, 512, SCAN_SMEM>>>(wf0, xg, hseq);

    // layer 1
    gemm_tf32_nt_bias<<<gemm_g4, 256>>>(hseq, W_ih1, b_ih1, b_hh1, xg, BT, G4, Hh);
    reset_scan_state<<<64, 256>>>();
    lstm_scan<<<NCTA, 512, SCAN_SMEM>>>(wf1, xg, hseq);

    // post: LN -> GELU -> Linear -> GELU -> LN
    ln_gelu_kernel<<<BT, 256>>>(hseq, ln1w, ln1b, act);
    gemm_tf32_nt_bias<<<gemm_h, 256>>>(act, linw, linb, nullptr, lin, BT, Hh, Hh);
    gelu_ln_kernel<<<BT, 256>>>(lin, ln2w, ln2b, out);
}

// round 6
// speedup vs baseline: 3.7014x; 1.1233x over previous
#include <cuda_runtime.h>
#include <math.h>
#include <stdint.h>
#include <stddef.h>

#define Bb 32
#define Tt 512
#define Dd 256
#define Hh 1024
#define G4 4096
#define BT (Bb*Tt)          // 16384
#define NCTA 128

// ---------------- scratch (device globals; no allocation allowed) ----------------
__device__ float g_xg[(size_t)BT * G4];     // 256 MB
__device__ float g_hseq[(size_t)BT * Hh];   // 64 MB
__device__ float g_hfrag[2 * Hh * Bb];      // h double buffer (tf32 bits, B-frag layout)
__device__ float g_wf0[(size_t)G4 * Hh];    // W_hh0 A-fragment layout (tf32 bits)
__device__ float g_wf1[(size_t)G4 * Hh];
__device__ unsigned int g_cnt;

#define PQ 1152                              // partial stride: 32 rows * 36
#define SCAN_SMEM ((8*PQ + 1024 + 8*33 + 32) * 4)

// ---------------- helpers ----------------
__device__ __forceinline__ float sigm(float x) { return 1.f / (1.f + expf(-x)); }
__device__ __forceinline__ float gelu_exact(float x) {
    return 0.5f * x * (1.f + erff(x * 0.70710678118654752440f));
}
__device__ __forceinline__ unsigned tf32_rna(float x) {
    unsigned r; asm("cvt.rna.tf32.f32 %0, %1;" : "=r"(r) : "f"(x)); return r;
}
__device__ __forceinline__ float tf32f(float x) { return __uint_as_float(tf32_rna(x)); }
__device__ __forceinline__ void mma_tf32(float c[4], const unsigned a[4],
                                         unsigned b0, unsigned b1) {
    asm("mma.sync.aligned.m16n8k8.row.col.f32.tf32.tf32.f32 "
        "{%0,%1,%2,%3},{%4,%5,%6,%7},{%8,%9},{%0,%1,%2,%3};"
        : "+f"(c[0]), "+f"(c[1]), "+f"(c[2]), "+f"(c[3])
        : "r"(a[0]), "r"(a[1]), "r"(a[2]), "r"(a[3]), "r"(b0), "r"(b1));
}

// ---------------- prep: W_hh[4H][H] -> per-CTA mma A-fragment layout ----------------
__global__ void prep_whh(const float* __restrict__ W, float* __restrict__ out) {
    int idx = blockIdx.x * 256 + threadIdx.x;
    int lane = idx & 31;
    int mt   = (idx >> 5) & 1;
    int kk   = (idx >> 6) & 127;
    int c    = idx >> 13;
    float tmp[4];
#pragma unroll
    for (int j = 0; j < 4; j++) {
        int rl = mt*16 + (lane >> 2) + ((j & 1) << 3);
        int k  = kk*8 + (lane & 3) + ((j >> 1) << 2);
        int R  = (rl >> 3) * 1024 + c*8 + (rl & 7);
        tmp[j] = __uint_as_float(tf32_rna(W[(size_t)R * Hh + k]));
    }
    ((float4*)out)[idx] = make_float4(tmp[0], tmp[1], tmp[2], tmp[3]);
}

// ---------------- reset ----------------
__global__ void reset_scan_state() {
    int i = blockIdx.x * blockDim.x + threadIdx.x;
    if (i == 0) g_cnt = 0u;
    for (int j = i; j < 2 * Hh * Bb; j += gridDim.x * blockDim.x) g_hfrag[j] = 0.f;
}

// ---------------- tf32 GEMM, fragment-native smem layout (unchanged from R5) ----------------
__global__ void __launch_bounds__(256) gemm_tf32_nt_bias(
    const float* __restrict__ A, const float* __restrict__ Bw,
    const float* __restrict__ b1, const float* __restrict__ b2,
    float* __restrict__ C, int M, int N, int K)
{
    __shared__ float As[2][2048];
    __shared__ float Bs[2][2048];

    const int tid  = threadIdx.x;
    const int lane = tid & 31;
    const int wid  = tid >> 5;
    const int bm   = blockIdx.y << 7;
    const int bn   = blockIdx.x << 7;
    const int wm   = (wid >> 2) << 6;
    const int wn   = (wid & 3) << 5;
    const int lr   = lane >> 2;
    const int lc   = lane & 3;

    const int mrow = tid >> 1;
    const int kk8  = tid & 1;
    const int khalf = kk8 << 3;

    const int a_off = (kk8*8 + (mrow >> 4))*128 + ((mrow >> 3) & 1)*32 + (mrow & 7)*4;
    const int b_off = (kk8*16 + (mrow >> 3))*64 + (mrow & 7)*4;

    const float* Ap = A + (size_t)(bm + mrow) * K + khalf;
    const float* Bp = Bw + (size_t)(bn + mrow) * K + khalf;

    float acc[4][4][4];
#pragma unroll
    for (int mt = 0; mt < 4; mt++)
#pragma unroll
        for (int nt = 0; nt < 4; nt++)
#pragma unroll
            for (int j = 0; j < 4; j++) acc[mt][nt][j] = 0.f;

    const int NC = K >> 4;
    float4 ra0, ra1, rb0, rb1;

    ra0 = *(const float4*)(Ap + 0);  ra1 = *(const float4*)(Ap + 4);
    rb0 = *(const float4*)(Bp + 0);  rb1 = *(const float4*)(Bp + 4);
    {
        float* as = &As[0][0]; float* bs = &Bs[0][0];
        *(float4*)(as + a_off)      = make_float4(tf32f(ra0.x), tf32f(ra0.y), tf32f(ra0.z), tf32f(ra0.w));
        *(float4*)(as + a_off + 64) = make_float4(tf32f(ra1.x), tf32f(ra1.y), tf32f(ra1.z), tf32f(ra1.w));
        *(float4*)(bs + b_off)      = make_float4(tf32f(rb0.x), tf32f(rb0.y), tf32f(rb0.z), tf32f(rb0.w));
        *(float4*)(bs + b_off + 32) = make_float4(tf32f(rb1.x), tf32f(rb1.y), tf32f(rb1.z), tf32f(rb1.w));
    }
    __syncthreads();

    for (int c = 0; c < NC; c++) {
        const int p = c & 1;
        if (c + 1 < NC) {
            const float* Apn = Ap + (size_t)(c + 1) * 16;
            const float* Bpn = Bp + (size_t)(c + 1) * 16;
            ra0 = *(const float4*)(Apn + 0);  ra1 = *(const float4*)(Apn + 4);
            rb0 = *(const float4*)(Bpn + 0);  rb1 = *(const float4*)(Bpn + 4);
        }

        const float* as = &As[p][0];
        const float* bs = &Bs[p][0];
#pragma unroll
        for (int ks = 0; ks < 2; ks++) {
            unsigned Af[4][4];
#pragma unroll
            for (int mt = 0; mt < 4; mt++) {
                const float* ap = as + (ks*8 + (wm >> 4) + mt)*128 + lane;
                Af[mt][0] = __float_as_uint(ap[0]);
                Af[mt][1] = __float_as_uint(ap[32]);
                Af[mt][2] = __float_as_uint(ap[64]);
                Af[mt][3] = __float_as_uint(ap[96]);
            }
            unsigned Bf[4][2];
#pragma unroll
            for (int nt = 0; nt < 4; nt++) {
                const float* bp = bs + (ks*16 + (wn >> 3) + nt)*64 + lane;
                Bf[nt][0] = __float_as_uint(bp[0]);
                Bf[nt][1] = __float_as_uint(bp[32]);
            }
#pragma unroll
            for (int mt = 0; mt < 4; mt++)
#pragma unroll
                for (int nt = 0; nt < 4; nt++)
                    mma_tf32(acc[mt][nt], Af[mt], Bf[nt][0], Bf[nt][1]);
        }

        if (c + 1 < NC) {
            float* asn = &As[1 - p][0]; float* bsn = &Bs[1 - p][0];
            *(float4*)(asn + a_off)      = make_float4(tf32f(ra0.x), tf32f(ra0.y), tf32f(ra0.z), tf32f(ra0.w));
            *(float4*)(asn + a_off + 64) = make_float4(tf32f(ra1.x), tf32f(ra1.y), tf32f(ra1.z), tf32f(ra1.w));
            *(float4*)(bsn + b_off)      = make_float4(tf32f(rb0.x), tf32f(rb0.y), tf32f(rb0.z), tf32f(rb0.w));
            *(float4*)(bsn + b_off + 32) = make_float4(tf32f(rb1.x), tf32f(rb1.y), tf32f(rb1.z), tf32f(rb1.w));
            __syncthreads();
        }
    }

#pragma unroll
    for (int nt = 0; nt < 4; nt++) {
        int col = bn + wn + nt*8 + lc*2;
        float bb0 = b1[col]     + (b2 ? b2[col]     : 0.f);
        float bb1 = b1[col + 1] + (b2 ? b2[col + 1] : 0.f);
#pragma unroll
        for (int mt = 0; mt < 4; mt++) {
            int row = bm + wm + mt*16 + lr;
            float2 v0 = make_float2(acc[mt][nt][0] + bb0, acc[mt][nt][1] + bb1);
            float2 v1 = make_float2(acc[mt][nt][2] + bb0, acc[mt][nt][3] + bb1);
            *(float2*)(C + (size_t)row * N + col)       = v0;
            *(float2*)(C + (size_t)(row + 8) * N + col) = v1;
        }
    }
}

// ---------------- persistent LSTM scan v3: 256 threads, K-split 8, W fully in regs ----------------
// 128 CTAs x 256 threads (8 warps, 2/SMSP). CTA owns units [c*8, c*8+8) = 32 gate rows.
// Warp kg handles K-chunk [kg*128, kg*128+128) = 16 octets; wreg[16][8] = 128 regs (no cap,
// 256 thr => 255-reg budget). 8 partials reduced via stride-36 smem (<=2-way conflicts).
__global__ void __launch_bounds__(256, 1) lstm_scan(
    const float* __restrict__ wf,
    const float* __restrict__ xg,
    float* __restrict__ hseq)
{
    extern __shared__ float smem[];
    float* part = smem;                          // 8 * PQ
    float* sXG  = part + 8*PQ;                   // 1024: [b][gate][u]
    float* sHT  = sXG + 1024;                    // 8*33: h transpose staging

    const int tid  = threadIdx.x;
    const int lane = tid & 31;
    const int kg   = tid >> 5;                   // warp id = K-group 0..7
    const int u0   = blockIdx.x * 8;

    // W fragments -> registers: 16 octets x 8 regs = 128 regs
    unsigned wreg[16][8];
    {
        const float4* wsrc = (const float4*)(wf + (size_t)blockIdx.x * 32768);
#pragma unroll
        for (int ks = 0; ks < 16; ks++) {
            int kk = kg*16 + ks;
            float4 w0 = wsrc[(kk*2+0)*32 + lane];
            float4 w1 = wsrc[(kk*2+1)*32 + lane];
            wreg[ks][0] = __float_as_uint(w0.x); wreg[ks][1] = __float_as_uint(w0.y);
            wreg[ks][2] = __float_as_uint(w0.z); wreg[ks][3] = __float_as_uint(w0.w);
            wreg[ks][4] = __float_as_uint(w1.x); wreg[ks][5] = __float_as_uint(w1.y);
            wreg[ks][6] = __float_as_uint(w1.z); wreg[ks][7] = __float_as_uint(w1.w);
        }
    }

    // xg staging: thread -> (batch pb, gate pg, 4-unit half ph)
    const int pb = tid >> 3;
    const int pg = (tid >> 1) & 3;
    const int ph = (tid & 1) << 2;
    const float* xg_base = xg + (size_t)pb * Tt * G4 + pg*1024 + u0 + ph;
    float4 px = *(const float4*)xg_base;

    const int uu = kg;                  // pointwise: warp == unit, lane == batch
    const int b  = lane;
    const int lr = lane >> 2;
    const int lc = lane & 3;
    float c_state = 0.f;
    unsigned bar = 0;

    for (int t = 0; t < Tt; t++) {
        // stage this step's xg, prefetch next
        {
            float* d = sXG + pb*32 + pg*8 + ph;
            d[0] = px.x; d[1] = px.y; d[2] = px.z; d[3] = px.w;
            int tn = (t + 1 < Tt) ? (t + 1) : t;
            px = *(const float4*)(xg_base + (size_t)tn * G4);
        }

        const int rp = t & 1;
        const float2* hb2 = (const float2*)(g_hfrag + rp * (Hh * Bb));

        float acc[2][4][4];
#pragma unroll
        for (int mt = 0; mt < 2; mt++)
#pragma unroll
            for (int nt = 0; nt < 4; nt++)
#pragma unroll
                for (int j = 0; j < 4; j++) acc[mt][nt][j] = 0.f;

        // h loads pipelined 2 octets ahead
        float2 hq[16][4];
#pragma unroll
        for (int pq = 0; pq < 2; pq++)
#pragma unroll
            for (int nt = 0; nt < 4; nt++)
                hq[pq][nt] = __ldcg(hb2 + ((kg*16 + pq)*4 + nt)*32 + lane);

#pragma unroll
        for (int ks = 0; ks < 16; ks++) {
            if (ks + 2 < 16) {
#pragma unroll
                for (int nt = 0; nt < 4; nt++)
                    hq[ks+2][nt] = __ldcg(hb2 + ((kg*16 + ks + 2)*4 + nt)*32 + lane);
            }
            unsigned A0[4] = {wreg[ks][0], wreg[ks][1], wreg[ks][2], wreg[ks][3]};
            unsigned A1[4] = {wreg[ks][4], wreg[ks][5], wreg[ks][6], wreg[ks][7]};
#pragma unroll
            for (int nt = 0; nt < 4; nt++) {
                unsigned b0 = __float_as_uint(hq[ks][nt].x);
                unsigned b1 = __float_as_uint(hq[ks][nt].y);
                mma_tf32(acc[0][nt], A0, b0, b1);
                mma_tf32(acc[1][nt], A1, b0, b1);
            }
        }

        // scatter 8 partials (STS.64, stride 36 => <=2-way conflicts)
#pragma unroll
        for (int mt = 0; mt < 2; mt++)
#pragma unroll
            for (int jh = 0; jh < 2; jh++) {
                int r = mt*16 + jh*8 + lr;
#pragma unroll
                for (int nt = 0; nt < 4; nt++) {
                    int n = nt*8 + lc*2;
                    *(float2*)(part + kg*PQ + r*36 + n) =
                        make_float2(acc[mt][nt][jh*2 + 0], acc[mt][nt][jh*2 + 1]);
                }
            }
        __syncthreads();

        // pointwise LSTM cell update: thread (uu, b), all 256 threads active
        float ga[4];
#pragma unroll
        for (int g = 0; g < 4; g++) {
            int roff = (g*8 + uu)*36 + b;
            float s = 0.f;
#pragma unroll
            for (int q = 0; q < 8; q++) s += part[q*PQ + roff];
            ga[g] = s + sXG[b*32 + g*8 + uu];
        }
        float ig = sigm(ga[0]);
        float fg = sigm(ga[1]);
        float gg = tanhf(ga[2]);
        float og = sigm(ga[3]);
        c_state = fg * c_state + ig * gg;
        float hval = og * tanhf(c_state);

        int u = u0 + uu;
        int pos = ((u >> 3)*4 + (b >> 3))*64 + ((b & 7)*4 + (u & 3))*2 + ((u >> 2) & 1);
        __stcg(g_hfrag + (1 - rp)*(Hh*Bb) + pos, __uint_as_float(tf32_rna(hval)));
        sHT[uu*33 + b] = hval;
        __syncthreads();

        // coalesced hseq write (8 consecutive floats per batch row)
        {
            int b_ = tid >> 3, uo = tid & 7;
            hseq[((size_t)b_ * Tt + t) * Hh + u0 + uo] = sHT[uo*33 + b_];
        }

        // grid barrier (128 CTAs, all resident), nanosleep backoff in poll
        if (tid == 0) {
            __threadfence();
            atomicAdd(&g_cnt, 1u);
            bar += NCTA;
            while (*((volatile unsigned int*)&g_cnt) < bar) { __nanosleep(40); }
            __threadfence();
        }
        __syncthreads();
    }
}

// ---------------- LayerNorm -> GELU ----------------
__global__ void ln_gelu_kernel(const float* __restrict__ X, const float* __restrict__ w,
                               const float* __restrict__ bv, float* __restrict__ Y)
{
    __shared__ float red[2][8];
    const int row = blockIdx.x;
    const int tid = threadIdx.x;
    float4 v = ((const float4*)(X + (size_t)row * Hh))[tid];
    float s = v.x + v.y + v.z + v.w;
    float q = v.x*v.x + v.y*v.y + v.z*v.z + v.w*v.w;
    int lane = tid & 31, wid = tid >> 5;
#pragma unroll
    for (int o = 16; o; o >>= 1) {
        s += __shfl_xor_sync(0xffffffffu, s, o);
        q += __shfl_xor_sync(0xffffffffu, q, o);
    }
    if (lane == 0) { red[0][wid] = s; red[1][wid] = q; }
    __syncthreads();
    if (wid == 0) {
        s = (lane < 8) ? red[0][lane] : 0.f;
        q = (lane < 8) ? red[1][lane] : 0.f;
#pragma unroll
        for (int o = 4; o; o >>= 1) {
            s += __shfl_xor_sync(0xffffffffu, s, o);
            q += __shfl_xor_sync(0xffffffffu, q, o);
        }
        if (lane == 0) { red[0][0] = s; red[1][0] = q; }
    }
    __syncthreads();
    float mu  = red[0][0] * (1.f / Hh);
    float var = red[1][0] * (1.f / Hh) - mu * mu;
    float rstd = rsqrtf(var + 1e-5f);
    float4 wv = ((const float4*)w)[tid];
    float4 bb = ((const float4*)bv)[tid];
    float4 y;
    y.x = gelu_exact((v.x - mu) * rstd * wv.x + bb.x);
    y.y = gelu_exact((v.y - mu) * rstd * wv.y + bb.y);
    y.z = gelu_exact((v.z - mu) * rstd * wv.z + bb.z);
    y.w = gelu_exact((v.w - mu) * rstd * wv.w + bb.w);
    ((float4*)(Y + (size_t)row * Hh))[tid] = y;
}

// ---------------- GELU -> LayerNorm ----------------
__global__ void gelu_ln_kernel(const float* __restrict__ X, const float* __restrict__ w,
                               const float* __restrict__ bv, float* __restrict__ Y)
{
    __shared__ float red[2][8];
    const int row = blockIdx.x;
    const int tid = threadIdx.x;
    float4 v = ((const float4*)(X + (size_t)row * Hh))[tid];
    v.x = gelu_exact(v.x); v.y = gelu_exact(v.y);
    v.z = gelu_exact(v.z); v.w = gelu_exact(v.w);
    float s = v.x + v.y + v.z + v.w;
    float q = v.x*v.x + v.y*v.y + v.z*v.z + v.w*v.w;
    int lane = tid & 31, wid = tid >> 5;
#pragma unroll
    for (int o = 16; o; o >>= 1) {
        s += __shfl_xor_sync(0xffffffffu, s, o);
        q += __shfl_xor_sync(0xffffffffu, q, o);
    }
    if (lane == 0) { red[0][wid] = s; red[1][wid] = q; }
    __syncthreads();
    if (wid == 0) {
        s = (lane < 8) ? red[0][lane] : 0.f;
        q = (lane < 8) ? red[1][lane] : 0.f;
#pragma unroll
        for (int o = 4; o; o >>= 1) {
            s += __shfl_xor_sync(0xffffffffu, s, o);
            q += __shfl_xor_sync(0xffffffffu, q, o);
        }
        if (lane == 0) { red[0][0] = s; red[1][0] = q; }
    }
    __syncthreads();
    float mu  = red[0][0] * (1.f / Hh);
    float var = red[1][0] * (1.f / Hh) - mu * mu;
    float rstd = rsqrtf(var + 1e-5f);
    float4 wv = ((const float4*)w)[tid];
    float4 bb = ((const float4*)bv)[tid];
    float4 y;
    y.x = (v.x - mu) * rstd * wv.x + bb.x;
    y.y = (v.y - mu) * rstd * wv.y + bb.y;
    y.z = (v.z - mu) * rstd * wv.z + bb.z;
    y.w = (v.w - mu) * rstd * wv.w + bb.w;
    ((float4*)(Y + (size_t)row * Hh))[tid] = y;
}

// ---------------- driver ----------------
extern "C" void kernel_launch(void* const* d_in, const int* in_sizes, int n_in,
                              void* d_out, int out_size)
{
    const float* bone  = (const float*)d_in[0];
    const float* W_ih0 = (const float*)d_in[1];
    const float* W_hh0 = (const float*)d_in[2];
    const float* b_ih0 = (const float*)d_in[3];
    const float* b_hh0 = (const float*)d_in[4];
    const float* W_ih1 = (const float*)d_in[5];
    const float* W_hh1 = (const float*)d_in[6];
    const float* b_ih1 = (const float*)d_in[7];
    const float* b_hh1 = (const float*)d_in[8];
    const float* ln1w  = (const float*)d_in[9];
    const float* ln1b  = (const float*)d_in[10];
    const float* linw  = (const float*)d_in[11];
    const float* linb  = (const float*)d_in[12];
    const float* ln2w  = (const float*)d_in[13];
    const float* ln2b  = (const float*)d_in[14];
    float* out = (float*)d_out;

    float *xg = nullptr, *hseq = nullptr, *wf0 = nullptr, *wf1 = nullptr;
    cudaGetSymbolAddress((void**)&xg, g_xg);
    cudaGetSymbolAddress((void**)&hseq, g_hseq);
    cudaGetSymbolAddress((void**)&wf0, g_wf0);
    cudaGetSymbolAddress((void**)&wf1, g_wf1);
    float* act = xg;
    float* lin = xg + (size_t)BT * Hh;

    cudaFuncSetAttribute(lstm_scan, cudaFuncAttributeMaxDynamicSharedMemorySize, SCAN_SMEM);

    dim3 gemm_g4(G4/128, BT/128);
    dim3 gemm_h(Hh/128, BT/128);

    prep_whh<<<4096, 256>>>(W_hh0, wf0);
    prep_whh<<<4096, 256>>>(W_hh1, wf1);

    // layer 0
    gemm_tf32_nt_bias<<<gemm_g4, 256>>>(bone, W_ih0, b_ih0, b_hh0, xg, BT, G4, Dd);
    reset_scan_state<<<64, 256>>>();
    lstm_scan<<<NCTA, 256, SCAN_SMEM>>>(wf0, xg, hseq);

    // layer 1
    gemm_tf32_nt_bias<<<gemm_g4, 256>>>(hseq, W_ih1, b_ih1, b_hh1, xg, BT, G4, Hh);
    reset_scan_state<<<64, 256>>>();
    lstm_scan<<<NCTA, 256, SCAN_SMEM>>>(wf1, xg, hseq);

    // post: LN -> GELU -> Linear -> GELU -> LN
    ln_gelu_kernel<<<BT, 256>>>(hseq, ln1w, ln1b, act);
    gemm_tf32_nt_bias<<<gemm_h, 256>>>(act, linw, linb, nullptr, lin, BT, Hh, Hh);
    gelu_ln_kernel<<<BT, 256>>>(lin, ln2w, ln2b, out);
}

// round 7
// speedup vs baseline: 4.1402x; 1.1185x over previous
#include <cuda_runtime.h>
#include <cuda_fp16.h>
#include <math.h>
#include <stdint.h>
#include <stddef.h>

#define Bb 32
#define Tt 512
#define Dd 256
#define Hh 1024
#define G4 4096
#define BT (Bb*Tt)          // 16384
#define NCTA 128

// ---------------- scratch (device globals; no allocation allowed) ----------------
__device__ float g_xg[(size_t)BT * G4];     // 256 MB
__device__ float g_hseq[(size_t)BT * Hh];   // 64 MB
__device__ __half g_h16[2 * 32768];         // h double buffer, fp16, B-frag layout
__device__ unsigned g_wf0[(size_t)NCTA * 16384];  // W_hh0 fp16 A-frags (8 MB)
__device__ unsigned g_wf1[(size_t)NCTA * 16384];
__device__ unsigned int g_cnt;

#define PQ 1152                              // partial stride: 32 rows * 36
#define SCAN_SMEM ((8*PQ + 1024 + 8*33 + 32) * 4)

// ---------------- helpers ----------------
__device__ __forceinline__ float sigm(float x) { return 1.f / (1.f + expf(-x)); }
__device__ __forceinline__ float gelu_exact(float x) {
    return 0.5f * x * (1.f + erff(x * 0.70710678118654752440f));
}
__device__ __forceinline__ unsigned tf32_rna(float x) {
    unsigned r; asm("cvt.rna.tf32.f32 %0, %1;" : "=r"(r) : "f"(x)); return r;
}
__device__ __forceinline__ float tf32f(float x) { return __uint_as_float(tf32_rna(x)); }
__device__ __forceinline__ void mma_tf32(float c[4], const unsigned a[4],
                                         unsigned b0, unsigned b1) {
    asm("mma.sync.aligned.m16n8k8.row.col.f32.tf32.tf32.f32 "
        "{%0,%1,%2,%3},{%4,%5,%6,%7},{%8,%9},{%0,%1,%2,%3};"
        : "+f"(c[0]), "+f"(c[1]), "+f"(c[2]), "+f"(c[3])
        : "r"(a[0]), "r"(a[1]), "r"(a[2]), "r"(a[3]), "r"(b0), "r"(b1));
}
__device__ __forceinline__ void mma_f16(float c[4], const unsigned a[4],
                                        unsigned b0, unsigned b1) {
    asm("mma.sync.aligned.m16n8k16.row.col.f32.f16.f16.f32 "
        "{%0,%1,%2,%3},{%4,%5,%6,%7},{%8,%9},{%0,%1,%2,%3};"
        : "+f"(c[0]), "+f"(c[1]), "+f"(c[2]), "+f"(c[3])
        : "r"(a[0]), "r"(a[1]), "r"(a[2]), "r"(a[3]), "r"(b0), "r"(b1));
}

// ---------------- prep: W_hh[4H][H] -> per-CTA fp16 m16n8k16 A-fragment layout ----------------
// out uint idx = c*16384 + ((kg*8+kc)*2+mt)*128 + j*32 + lane
// element: rows rl = mt*16 + (lane>>2) + ((j&1)<<3)   (CTA-local gate-row, R = gate*1024 + u0+uu)
//          k  = kg*128 + kc*16 + ((j>>1)<<3) + ((lane&3)<<1) + {0,1}   (half2)
__global__ void prep_whh_f16(const float* __restrict__ W, unsigned* __restrict__ out) {
    int idx = blockIdx.x * 256 + threadIdx.x;    // 2,097,152 total
    int lane = idx & 31;
    int j    = (idx >> 5) & 3;
    int mt   = (idx >> 7) & 1;
    int kc   = (idx >> 8) & 7;
    int kg   = (idx >> 11) & 7;
    int c    = idx >> 14;
    int rl = mt*16 + (lane >> 2) + ((j & 1) << 3);
    int R  = (rl >> 3) * 1024 + c*8 + (rl & 7);
    int k0 = kg*128 + kc*16 + ((j >> 1) << 3) + ((lane & 3) << 1);
    __half2 v = __floats2half2_rn(W[(size_t)R * Hh + k0], W[(size_t)R * Hh + k0 + 1]);
    out[idx] = *(unsigned*)&v;
}

// ---------------- reset ----------------
__global__ void reset_scan_state() {
    int i = blockIdx.x * blockDim.x + threadIdx.x;
    if (i == 0) g_cnt = 0u;
    for (int j = i; j < 2 * 32768 / 2; j += gridDim.x * blockDim.x)
        ((__half2*)g_h16)[j] = __half2half2(__float2half(0.f));
}

// ---------------- tf32 GEMM, fragment-native smem layout (unchanged) ----------------
__global__ void __launch_bounds__(256) gemm_tf32_nt_bias(
    const float* __restrict__ A, const float* __restrict__ Bw,
    const float* __restrict__ b1, const float* __restrict__ b2,
    float* __restrict__ C, int M, int N, int K)
{
    __shared__ float As[2][2048];
    __shared__ float Bs[2][2048];

    const int tid  = threadIdx.x;
    const int lane = tid & 31;
    const int wid  = tid >> 5;
    const int bm   = blockIdx.y << 7;
    const int bn   = blockIdx.x << 7;
    const int wm   = (wid >> 2) << 6;
    const int wn   = (wid & 3) << 5;
    const int lr   = lane >> 2;
    const int lc   = lane & 3;

    const int mrow = tid >> 1;
    const int kk8  = tid & 1;
    const int khalf = kk8 << 3;

    const int a_off = (kk8*8 + (mrow >> 4))*128 + ((mrow >> 3) & 1)*32 + (mrow & 7)*4;
    const int b_off = (kk8*16 + (mrow >> 3))*64 + (mrow & 7)*4;

    const float* Ap = A + (size_t)(bm + mrow) * K + khalf;
    const float* Bp = Bw + (size_t)(bn + mrow) * K + khalf;

    float acc[4][4][4];
#pragma unroll
    for (int mt = 0; mt < 4; mt++)
#pragma unroll
        for (int nt = 0; nt < 4; nt++)
#pragma unroll
            for (int j = 0; j < 4; j++) acc[mt][nt][j] = 0.f;

    const int NC = K >> 4;
    float4 ra0, ra1, rb0, rb1;

    ra0 = *(const float4*)(Ap + 0);  ra1 = *(const float4*)(Ap + 4);
    rb0 = *(const float4*)(Bp + 0);  rb1 = *(const float4*)(Bp + 4);
    {
        float* as = &As[0][0]; float* bs = &Bs[0][0];
        *(float4*)(as + a_off)      = make_float4(tf32f(ra0.x), tf32f(ra0.y), tf32f(ra0.z), tf32f(ra0.w));
        *(float4*)(as + a_off + 64) = make_float4(tf32f(ra1.x), tf32f(ra1.y), tf32f(ra1.z), tf32f(ra1.w));
        *(float4*)(bs + b_off)      = make_float4(tf32f(rb0.x), tf32f(rb0.y), tf32f(rb0.z), tf32f(rb0.w));
        *(float4*)(bs + b_off + 32) = make_float4(tf32f(rb1.x), tf32f(rb1.y), tf32f(rb1.z), tf32f(rb1.w));
    }
    __syncthreads();

    for (int c = 0; c < NC; c++) {
        const int p = c & 1;
        if (c + 1 < NC) {
            const float* Apn = Ap + (size_t)(c + 1) * 16;
            const float* Bpn = Bp + (size_t)(c + 1) * 16;
            ra0 = *(const float4*)(Apn + 0);  ra1 = *(const float4*)(Apn + 4);
            rb0 = *(const float4*)(Bpn + 0);  rb1 = *(const float4*)(Bpn + 4);
        }

        const float* as = &As[p][0];
        const float* bs = &Bs[p][0];
#pragma unroll
        for (int ks = 0; ks < 2; ks++) {
            unsigned Af[4][4];
#pragma unroll
            for (int mt = 0; mt < 4; mt++) {
                const float* ap = as + (ks*8 + (wm >> 4) + mt)*128 + lane;
                Af[mt][0] = __float_as_uint(ap[0]);
                Af[mt][1] = __float_as_uint(ap[32]);
                Af[mt][2] = __float_as_uint(ap[64]);
                Af[mt][3] = __float_as_uint(ap[96]);
            }
            unsigned Bf[4][2];
#pragma unroll
            for (int nt = 0; nt < 4; nt++) {
                const float* bp = bs + (ks*16 + (wn >> 3) + nt)*64 + lane;
                Bf[nt][0] = __float_as_uint(bp[0]);
                Bf[nt][1] = __float_as_uint(bp[32]);
            }
#pragma unroll
            for (int mt = 0; mt < 4; mt++)
#pragma unroll
                for (int nt = 0; nt < 4; nt++)
                    mma_tf32(acc[mt][nt], Af[mt], Bf[nt][0], Bf[nt][1]);
        }

        if (c + 1 < NC) {
            float* asn = &As[1 - p][0]; float* bsn = &Bs[1 - p][0];
            *(float4*)(asn + a_off)      = make_float4(tf32f(ra0.x), tf32f(ra0.y), tf32f(ra0.z), tf32f(ra0.w));
            *(float4*)(asn + a_off + 64) = make_float4(tf32f(ra1.x), tf32f(ra1.y), tf32f(ra1.z), tf32f(ra1.w));
            *(float4*)(bsn + b_off)      = make_float4(tf32f(rb0.x), tf32f(rb0.y), tf32f(rb0.z), tf32f(rb0.w));
            *(float4*)(bsn + b_off + 32) = make_float4(tf32f(rb1.x), tf32f(rb1.y), tf32f(rb1.z), tf32f(rb1.w));
            __syncthreads();
        }
    }

#pragma unroll
    for (int nt = 0; nt < 4; nt++) {
        int col = bn + wn + nt*8 + lc*2;
        float bb0 = b1[col]     + (b2 ? b2[col]     : 0.f);
        float bb1 = b1[col + 1] + (b2 ? b2[col + 1] : 0.f);
#pragma unroll
        for (int mt = 0; mt < 4; mt++) {
            int row = bm + wm + mt*16 + lr;
            float2 v0 = make_float2(acc[mt][nt][0] + bb0, acc[mt][nt][1] + bb1);
            float2 v1 = make_float2(acc[mt][nt][2] + bb0, acc[mt][nt][3] + bb1);
            *(float2*)(C + (size_t)row * N + col)       = v0;
            *(float2*)(C + (size_t)(row + 8) * N + col) = v1;
        }
    }
}

// ---------------- persistent LSTM scan v4: fp16 m16n8k16 recurrence ----------------
// 128 CTAs x 256 threads (8 warps). CTA owns units [c*8, c*8+8) = 32 gate rows.
// Warp kg: K-chunk [kg*128, kg*128+128) = 8 k16-chunks; W fp16 frags in 64 regs.
// All 64 h uints loaded up front each step (max MLP), then 64 mma back-to-back.
// h buffer layout (uint granularity): idx = ((kcg*2+hh)*32 + n)*4 + (lane&3-slot)
__global__ void __launch_bounds__(256, 1) lstm_scan(
    const unsigned* __restrict__ wf,
    const float* __restrict__ xg,
    float* __restrict__ hseq)
{
    extern __shared__ float smem[];
    float* part = smem;                          // 8 * PQ
    float* sXG  = part + 8*PQ;                   // 1024: [b][gate][u]
    float* sHT  = sXG + 1024;                    // 8*33

    const int tid  = threadIdx.x;
    const int lane = tid & 31;
    const int kg   = tid >> 5;
    const int u0   = blockIdx.x * 8;

    // W fp16 fragments -> 64 registers
    unsigned wreg[8][2][4];
    {
        const unsigned* wb = wf + (size_t)blockIdx.x * 16384;
#pragma unroll
        for (int kc = 0; kc < 8; kc++)
#pragma unroll
            for (int mt = 0; mt < 2; mt++)
#pragma unroll
                for (int j = 0; j < 4; j++)
                    wreg[kc][mt][j] = wb[((kg*8 + kc)*2 + mt)*128 + j*32 + lane];
    }

    // xg staging
    const int pb = tid >> 3;
    const int pg = (tid >> 1) & 3;
    const int ph = (tid & 1) << 2;
    const float* xg_base = xg + (size_t)pb * Tt * G4 + pg*1024 + u0 + ph;
    float4 px = *(const float4*)xg_base;

    const int uu = kg;
    const int b  = lane;
    const int lr = lane >> 2;
    const int lc = lane & 3;
    float c_state = 0.f;
    unsigned bar = 0;

    // precomputed h-write address pieces (u fixed per thread)
    const int u = u0 + uu;
    const int w_kcg = u >> 4;
    const int w_hh  = (u >> 3) & 1;
    const int w_l4  = (u & 7) >> 1;
    const int w_pos = u & 1;
    const int w_idx = ((((w_kcg*2 + w_hh)*32 + b)*4 + w_l4) << 1) + w_pos;

    for (int t = 0; t < Tt; t++) {
        {
            float* d = sXG + pb*32 + pg*8 + ph;
            d[0] = px.x; d[1] = px.y; d[2] = px.z; d[3] = px.w;
            int tn = (t + 1 < Tt) ? (t + 1) : t;
            px = *(const float4*)(xg_base + (size_t)tn * G4);
        }

        const int rp = t & 1;
        const unsigned* hb = (const unsigned*)g_h16 + rp * 16384;

        // load ALL h fragments for this warp's K range up front
        unsigned hq[8][4][2];
#pragma unroll
        for (int kc = 0; kc < 8; kc++) {
            const int kcg = kg*8 + kc;
#pragma unroll
            for (int nt = 0; nt < 4; nt++) {
                hq[kc][nt][0] = __ldcg(hb + ((kcg*2 + 0)*32 + nt*8 + lr)*4 + lc);
                hq[kc][nt][1] = __ldcg(hb + ((kcg*2 + 1)*32 + nt*8 + lr)*4 + lc);
            }
        }

        float acc[2][4][4];
#pragma unroll
        for (int mt = 0; mt < 2; mt++)
#pragma unroll
            for (int nt = 0; nt < 4; nt++)
#pragma unroll
                for (int j = 0; j < 4; j++) acc[mt][nt][j] = 0.f;

#pragma unroll
        for (int kc = 0; kc < 8; kc++) {
#pragma unroll
            for (int nt = 0; nt < 4; nt++) {
                mma_f16(acc[0][nt], wreg[kc][0], hq[kc][nt][0], hq[kc][nt][1]);
                mma_f16(acc[1][nt], wreg[kc][1], hq[kc][nt][0], hq[kc][nt][1]);
            }
        }

        // scatter 8 partials (STS.64, stride 36)
#pragma unroll
        for (int mt = 0; mt < 2; mt++)
#pragma unroll
            for (int jh = 0; jh < 2; jh++) {
                int r = mt*16 + jh*8 + lr;
#pragma unroll
                for (int nt = 0; nt < 4; nt++) {
                    int n = nt*8 + lc*2;
                    *(float2*)(part + kg*PQ + r*36 + n) =
                        make_float2(acc[mt][nt][jh*2 + 0], acc[mt][nt][jh*2 + 1]);
                }
            }
        __syncthreads();

        // pointwise LSTM cell
        float ga[4];
#pragma unroll
        for (int g = 0; g < 4; g++) {
            int roff = (g*8 + uu)*36 + b;
            float s = 0.f;
#pragma unroll
            for (int q = 0; q < 8; q++) s += part[q*PQ + roff];
            ga[g] = s + sXG[b*32 + g*8 + uu];
        }
        float ig = sigm(ga[0]);
        float fg = sigm(ga[1]);
        float gg = tanhf(ga[2]);
        float og = sigm(ga[3]);
        c_state = fg * c_state + ig * gg;
        float hval = og * tanhf(c_state);

        g_h16[(1 - rp)*32768 + w_idx] = __float2half_rn(hval);
        sHT[uu*33 + b] = hval;
        __syncthreads();

        {
            int b_ = tid >> 3, uo = tid & 7;
            hseq[((size_t)b_ * Tt + t) * Hh + u0 + uo] = sHT[uo*33 + b_];
        }

        if (tid == 0) {
            __threadfence();
            atomicAdd(&g_cnt, 1u);
            bar += NCTA;
            while (*((volatile unsigned int*)&g_cnt) < bar) { __nanosleep(40); }
            __threadfence();
        }
        __syncthreads();
    }
}

// ---------------- LayerNorm -> GELU ----------------
__global__ void ln_gelu_kernel(const float* __restrict__ X, const float* __restrict__ w,
                               const float* __restrict__ bv, float* __restrict__ Y)
{
    __shared__ float red[2][8];
    const int row = blockIdx.x;
    const int tid = threadIdx.x;
    float4 v = ((const float4*)(X + (size_t)row * Hh))[tid];
    float s = v.x + v.y + v.z + v.w;
    float q = v.x*v.x + v.y*v.y + v.z*v.z + v.w*v.w;
    int lane = tid & 31, wid = tid >> 5;
#pragma unroll
    for (int o = 16; o; o >>= 1) {
        s += __shfl_xor_sync(0xffffffffu, s, o);
        q += __shfl_xor_sync(0xffffffffu, q, o);
    }
    if (lane == 0) { red[0][wid] = s; red[1][wid] = q; }
    __syncthreads();
    if (wid == 0) {
        s = (lane < 8) ? red[0][lane] : 0.f;
        q = (lane < 8) ? red[1][lane] : 0.f;
#pragma unroll
        for (int o = 4; o; o >>= 1) {
            s += __shfl_xor_sync(0xffffffffu, s, o);
            q += __shfl_xor_sync(0xffffffffu, q, o);
        }
        if (lane == 0) { red[0][0] = s; red[1][0] = q; }
    }
    __syncthreads();
    float mu  = red[0][0] * (1.f / Hh);
    float var = red[1][0] * (1.f / Hh) - mu * mu;
    float rstd = rsqrtf(var + 1e-5f);
    float4 wv = ((const float4*)w)[tid];
    float4 bb = ((const float4*)bv)[tid];
    float4 y;
    y.x = gelu_exact((v.x - mu) * rstd * wv.x + bb.x);
    y.y = gelu_exact((v.y - mu) * rstd * wv.y + bb.y);
    y.z = gelu_exact((v.z - mu) * rstd * wv.z + bb.z);
    y.w = gelu_exact((v.w - mu) * rstd * wv.w + bb.w);
    ((float4*)(Y + (size_t)row * Hh))[tid] = y;
}

// ---------------- GELU -> LayerNorm ----------------
__global__ void gelu_ln_kernel(const float* __restrict__ X, const float* __restrict__ w,
                               const float* __restrict__ bv, float* __restrict__ Y)
{
    __shared__ float red[2][8];
    const int row = blockIdx.x;
    const int tid = threadIdx.x;
    float4 v = ((const float4*)(X + (size_t)row * Hh))[tid];
    v.x = gelu_exact(v.x); v.y = gelu_exact(v.y);
    v.z = gelu_exact(v.z); v.w = gelu_exact(v.w);
    float s = v.x + v.y + v.z + v.w;
    float q = v.x*v.x + v.y*v.y + v.z*v.z + v.w*v.w;
    int lane = tid & 31, wid = tid >> 5;
#pragma unroll
    for (int o = 16; o; o >>= 1) {
        s += __shfl_xor_sync(0xffffffffu, s, o);
        q += __shfl_xor_sync(0xffffffffu, q, o);
    }
    if (lane == 0) { red[0][wid] = s; red[1][wid] = q; }
    __syncthreads();
    if (wid == 0) {
        s = (lane < 8) ? red[0][lane] : 0.f;
        q = (lane < 8) ? red[1][lane] : 0.f;
#pragma unroll
        for (int o = 4; o; o >>= 1) {
            s += __shfl_xor_sync(0xffffffffu, s, o);
            q += __shfl_xor_sync(0xffffffffu, q, o);
        }
        if (lane == 0) { red[0][0] = s; red[1][0] = q; }
    }
    __syncthreads();
    float mu  = red[0][0] * (1.f / Hh);
    float var = red[1][0] * (1.f / Hh) - mu * mu;
    float rstd = rsqrtf(var + 1e-5f);
    float4 wv = ((const float4*)w)[tid];
    float4 bb = ((const float4*)bv)[tid];
    float4 y;
    y.x = (v.x - mu) * rstd * wv.x + bb.x;
    y.y = (v.y - mu) * rstd * wv.y + bb.y;
    y.z = (v.z - mu) * rstd * wv.z + bb.z;
    y.w = (v.w - mu) * rstd * wv.w + bb.w;
    ((float4*)(Y + (size_t)row * Hh))[tid] = y;
}

// ---------------- driver ----------------
extern "C" void kernel_launch(void* const* d_in, const int* in_sizes, int n_in,
                              void* d_out, int out_size)
{
    const float* bone  = (const float*)d_in[0];
    const float* W_ih0 = (const float*)d_in[1];
    const float* W_hh0 = (const float*)d_in[2];
    const float* b_ih0 = (const float*)d_in[3];
    const float* b_hh0 = (const float*)d_in[4];
    const float* W_ih1 = (const float*)d_in[5];
    const float* W_hh1 = (const float*)d_in[6];
    const float* b_ih1 = (const float*)d_in[7];
    const float* b_hh1 = (const float*)d_in[8];
    const float* ln1w  = (const float*)d_in[9];
    const float* ln1b  = (const float*)d_in[10];
    const float* linw  = (const float*)d_in[11];
    const float* linb  = (const float*)d_in[12];
    const float* ln2w  = (const float*)d_in[13];
    const float* ln2b  = (const float*)d_in[14];
    float* out = (float*)d_out;

    float *xg = nullptr, *hseq = nullptr;
    unsigned *wf0 = nullptr, *wf1 = nullptr;
    cudaGetSymbolAddress((void**)&xg, g_xg);
    cudaGetSymbolAddress((void**)&hseq, g_hseq);
    cudaGetSymbolAddress((void**)&wf0, g_wf0);
    cudaGetSymbolAddress((void**)&wf1, g_wf1);
    float* act = xg;
    float* lin = xg + (size_t)BT * Hh;

    cudaFuncSetAttribute(lstm_scan, cudaFuncAttributeMaxDynamicSharedMemorySize, SCAN_SMEM);

    dim3 gemm_g4(G4/128, BT/128);
    dim3 gemm_h(Hh/128, BT/128);

    prep_whh_f16<<<8192, 256>>>(W_hh0, wf0);
    prep_whh_f16<<<8192, 256>>>(W_hh1, wf1);

    // layer 0
    gemm_tf32_nt_bias<<<gemm_g4, 256>>>(bone, W_ih0, b_ih0, b_hh0, xg, BT, G4, Dd);
    reset_scan_state<<<64, 256>>>();
    lstm_scan<<<NCTA, 256, SCAN_SMEM>>>(wf0, xg, hseq);

    // layer 1
    gemm_tf32_nt_bias<<<gemm_g4, 256>>>(hseq, W_ih1, b_ih1, b_hh1, xg, BT, G4, Hh);
    reset_scan_state<<<64, 256>>>();
    lstm_scan<<<NCTA, 256, SCAN_SMEM>>>(wf1, xg, hseq);

    // post: LN -> GELU -> Linear -> GELU -> LN
    ln_gelu_kernel<<<BT, 256>>>(hseq, ln1w, ln1b, act);
    gemm_tf32_nt_bias<<<gemm_h, 256>>>(act, linw, linb, nullptr, lin, BT, Hh, Hh);
    gelu_ln_kernel<<<BT, 256>>>(lin, ln2w, ln2b, out);
}

// round 8
// speedup vs baseline: 4.5836x; 1.1071x over previous
#include <cuda_runtime.h>
#include <cuda_fp16.h>
#include <math.h>
#include <stdint.h>
#include <stddef.h>

#define Bb 32
#define Tt 512
#define Dd 256
#define Hh 1024
#define G4 4096
#define BT (Bb*Tt)          // 16384
#define NCTA 128

// ---------------- scratch (device globals; no allocation allowed) ----------------
__device__ float g_xg[(size_t)BT * G4];     // 256 MB
__device__ float g_hseq[(size_t)BT * Hh];   // 64 MB
__device__ __half g_h16[2 * 32768];         // h double buffer, fp16, B-frag layout
__device__ unsigned g_wf0[(size_t)NCTA * 16384];  // W_hh0 fp16 A-frags (8 MB)
__device__ unsigned g_wf1[(size_t)NCTA * 16384];
__device__ unsigned int g_cnt;

#define PQ 1152                              // partial stride: 32 rows * 36
#define SCAN_SMEM ((8*PQ + 1024 + 8*33 + 32) * 4)

// ---------------- helpers ----------------
__device__ __forceinline__ float sigm(float x) { return 1.f / (1.f + expf(-x)); }
__device__ __forceinline__ float gelu_exact(float x) {
    return 0.5f * x * (1.f + erff(x * 0.70710678118654752440f));
}
__device__ __forceinline__ void mma_f16(float c[4], const unsigned a[4],
                                        unsigned b0, unsigned b1) {
    asm("mma.sync.aligned.m16n8k16.row.col.f32.f16.f16.f32 "
        "{%0,%1,%2,%3},{%4,%5,%6,%7},{%8,%9},{%0,%1,%2,%3};"
        : "+f"(c[0]), "+f"(c[1]), "+f"(c[2]), "+f"(c[3])
        : "r"(a[0]), "r"(a[1]), "r"(a[2]), "r"(a[3]), "r"(b0), "r"(b1));
}
__device__ __forceinline__ unsigned pack_h2(float a, float b) {
    __half2 h = __floats2half2_rn(a, b);
    return *(unsigned*)&h;
}

// ---------------- prep: W_hh[4H][H] -> per-CTA fp16 m16n8k16 A-fragment layout ----------------
__global__ void prep_whh_f16(const float* __restrict__ W, unsigned* __restrict__ out) {
    int idx = blockIdx.x * 256 + threadIdx.x;    // 2,097,152 total
    int lane = idx & 31;
    int j    = (idx >> 5) & 3;
    int mt   = (idx >> 7) & 1;
    int kc   = (idx >> 8) & 7;
    int kg   = (idx >> 11) & 7;
    int c    = idx >> 14;
    int rl = mt*16 + (lane >> 2) + ((j & 1) << 3);
    int R  = (rl >> 3) * 1024 + c*8 + (rl & 7);
    int k0 = kg*128 + kc*16 + ((j >> 1) << 3) + ((lane & 3) << 1);
    out[idx] = pack_h2(W[(size_t)R * Hh + k0], W[(size_t)R * Hh + k0 + 1]);
}

// ---------------- reset ----------------
__global__ void reset_scan_state() {
    int i = blockIdx.x * blockDim.x + threadIdx.x;
    if (i == 0) g_cnt = 0u;
    for (int j = i; j < 2 * 32768 / 2; j += gridDim.x * blockDim.x)
        ((__half2*)g_h16)[j] = __half2half2(__float2half(0.f));
}

// ---------------- fp16 GEMM (m16n8k16), fragment-native smem, j-stride 40 ----------------
// C[m][n] = sum_k A[m][k]*Bw[n][k] + b1[n] (+b2[n]). M,N mult of 128, K mult of 16.
// 256 threads, block tile 128x128, warp tile 64x32 (2x4 warps), K-chunk 16, dbl buffer.
// A smem uint idx = mtile*160 + j*40 + lane,  j = (row>>3 &1) + 2*kk8
// B smem uint idx = ntile*80  + j*40 + lane,  j = kk8
#define ACH 1280
#define BCH 1280
__global__ void __launch_bounds__(256) gemm_f16_nt_bias(
    const float* __restrict__ A, const float* __restrict__ Bw,
    const float* __restrict__ b1, const float* __restrict__ b2,
    float* __restrict__ C, int M, int N, int K)
{
    __shared__ unsigned As[2][ACH];
    __shared__ unsigned Bs[2][BCH];

    const int tid  = threadIdx.x;
    const int lane = tid & 31;
    const int wid  = tid >> 5;
    const int bm   = blockIdx.y << 7;
    const int bn   = blockIdx.x << 7;
    const int wm   = (wid >> 2) << 6;      // 0 / 64
    const int wn   = (wid & 3) << 5;       // 0/32/64/96
    const int lr   = lane >> 2;
    const int lc   = lane & 3;

    const int mrow = tid >> 1;             // 0..127
    const int kk8  = tid & 1;              // k-octet within 16-chunk

    const int a_off = (mrow >> 4)*160 + (((mrow >> 3) & 1) + 2*kk8)*40 + (mrow & 7)*4;
    const int b_off = (mrow >> 3)*80 + kk8*40 + (mrow & 7)*4;

    const float* Ap = A + (size_t)(bm + mrow) * K + kk8*8;
    const float* Bp = Bw + (size_t)(bn + mrow) * K + kk8*8;

    float acc[4][4][4];
#pragma unroll
    for (int mt = 0; mt < 4; mt++)
#pragma unroll
        for (int nt = 0; nt < 4; nt++)
#pragma unroll
            for (int j = 0; j < 4; j++) acc[mt][nt][j] = 0.f;

    const int NC = K >> 4;
    float4 ra0, ra1, rb0, rb1;

    // prologue: chunk 0
    ra0 = *(const float4*)(Ap + 0);  ra1 = *(const float4*)(Ap + 4);
    rb0 = *(const float4*)(Bp + 0);  rb1 = *(const float4*)(Bp + 4);
    {
        unsigned* as = &As[0][0]; unsigned* bs = &Bs[0][0];
        *(uint4*)(as + a_off) = make_uint4(pack_h2(ra0.x, ra0.y), pack_h2(ra0.z, ra0.w),
                                           pack_h2(ra1.x, ra1.y), pack_h2(ra1.z, ra1.w));
        *(uint4*)(bs + b_off) = make_uint4(pack_h2(rb0.x, rb0.y), pack_h2(rb0.z, rb0.w),
                                           pack_h2(rb1.x, rb1.y), pack_h2(rb1.z, rb1.w));
    }
    __syncthreads();

    for (int c = 0; c < NC; c++) {
        const int p = c & 1;
        if (c + 1 < NC) {
            const float* Apn = Ap + (size_t)(c + 1) * 16;
            const float* Bpn = Bp + (size_t)(c + 1) * 16;
            ra0 = *(const float4*)(Apn + 0);  ra1 = *(const float4*)(Apn + 4);
            rb0 = *(const float4*)(Bpn + 0);  rb1 = *(const float4*)(Bpn + 4);
        }

        const unsigned* as = &As[p][0];
        const unsigned* bs = &Bs[p][0];

        unsigned Af[4][4];
#pragma unroll
        for (int mt = 0; mt < 4; mt++) {
            const unsigned* ap = as + ((wm >> 4) + mt)*160 + lane;
            Af[mt][0] = ap[0];
            Af[mt][1] = ap[40];
            Af[mt][2] = ap[80];
            Af[mt][3] = ap[120];
        }
        unsigned Bf[4][2];
#pragma unroll
        for (int nt = 0; nt < 4; nt++) {
            const unsigned* bp = bs + ((wn >> 3) + nt)*80 + lane;
            Bf[nt][0] = bp[0];
            Bf[nt][1] = bp[40];
        }
#pragma unroll
        for (int mt = 0; mt < 4; mt++)
#pragma unroll
            for (int nt = 0; nt < 4; nt++)
                mma_f16(acc[mt][nt], Af[mt], Bf[nt][0], Bf[nt][1]);

        if (c + 1 < NC) {
            unsigned* asn = &As[1 - p][0]; unsigned* bsn = &Bs[1 - p][0];
            *(uint4*)(asn + a_off) = make_uint4(pack_h2(ra0.x, ra0.y), pack_h2(ra0.z, ra0.w),
                                                pack_h2(ra1.x, ra1.y), pack_h2(ra1.z, ra1.w));
            *(uint4*)(bsn + b_off) = make_uint4(pack_h2(rb0.x, rb0.y), pack_h2(rb0.z, rb0.w),
                                                pack_h2(rb1.x, rb1.y), pack_h2(rb1.z, rb1.w));
            __syncthreads();
        }
    }

    // epilogue: bias + store
#pragma unroll
    for (int nt = 0; nt < 4; nt++) {
        int col = bn + wn + nt*8 + lc*2;
        float bb0 = b1[col]     + (b2 ? b2[col]     : 0.f);
        float bb1 = b1[col + 1] + (b2 ? b2[col + 1] : 0.f);
#pragma unroll
        for (int mt = 0; mt < 4; mt++) {
            int row = bm + wm + mt*16 + lr;
            float2 v0 = make_float2(acc[mt][nt][0] + bb0, acc[mt][nt][1] + bb1);
            float2 v1 = make_float2(acc[mt][nt][2] + bb0, acc[mt][nt][3] + bb1);
            *(float2*)(C + (size_t)row * N + col)       = v0;
            *(float2*)(C + (size_t)(row + 8) * N + col) = v1;
        }
    }
}

// ---------------- persistent LSTM scan v4: fp16 m16n8k16 recurrence (unchanged) ----------------
__global__ void __launch_bounds__(256, 1) lstm_scan(
    const unsigned* __restrict__ wf,
    const float* __restrict__ xg,
    float* __restrict__ hseq)
{
    extern __shared__ float smem[];
    float* part = smem;                          // 8 * PQ
    float* sXG  = part + 8*PQ;                   // 1024: [b][gate][u]
    float* sHT  = sXG + 1024;                    // 8*33

    const int tid  = threadIdx.x;
    const int lane = tid & 31;
    const int kg   = tid >> 5;
    const int u0   = blockIdx.x * 8;

    // W fp16 fragments -> 64 registers
    unsigned wreg[8][2][4];
    {
        const unsigned* wb = wf + (size_t)blockIdx.x * 16384;
#pragma unroll
        for (int kc = 0; kc < 8; kc++)
#pragma unroll
            for (int mt = 0; mt < 2; mt++)
#pragma unroll
                for (int j = 0; j < 4; j++)
                    wreg[kc][mt][j] = wb[((kg*8 + kc)*2 + mt)*128 + j*32 + lane];
    }

    // xg staging
    const int pb = tid >> 3;
    const int pg = (tid >> 1) & 3;
    const int ph = (tid & 1) << 2;
    const float* xg_base = xg + (size_t)pb * Tt * G4 + pg*1024 + u0 + ph;
    float4 px = *(const float4*)xg_base;

    const int uu = kg;
    const int b  = lane;
    const int lr = lane >> 2;
    const int lc = lane & 3;
    float c_state = 0.f;
    unsigned bar = 0;

    const int u = u0 + uu;
    const int w_kcg = u >> 4;
    const int w_hh  = (u >> 3) & 1;
    const int w_l4  = (u & 7) >> 1;
    const int w_pos = u & 1;
    const int w_idx = ((((w_kcg*2 + w_hh)*32 + b)*4 + w_l4) << 1) + w_pos;

    for (int t = 0; t < Tt; t++) {
        {
            float* d = sXG + pb*32 + pg*8 + ph;
            d[0] = px.x; d[1] = px.y; d[2] = px.z; d[3] = px.w;
            int tn = (t + 1 < Tt) ? (t + 1) : t;
            px = *(const float4*)(xg_base + (size_t)tn * G4);
        }

        const int rp = t & 1;
        const unsigned* hb = (const unsigned*)g_h16 + rp * 16384;

        unsigned hq[8][4][2];
#pragma unroll
        for (int kc = 0; kc < 8; kc++) {
            const int kcg = kg*8 + kc;
#pragma unroll
            for (int nt = 0; nt < 4; nt++) {
                hq[kc][nt][0] = __ldcg(hb + ((kcg*2 + 0)*32 + nt*8 + lr)*4 + lc);
                hq[kc][nt][1] = __ldcg(hb + ((kcg*2 + 1)*32 + nt*8 + lr)*4 + lc);
            }
        }

        float acc[2][4][4];
#pragma unroll
        for (int mt = 0; mt < 2; mt++)
#pragma unroll
            for (int nt = 0; nt < 4; nt++)
#pragma unroll
                for (int j = 0; j < 4; j++) acc[mt][nt][j] = 0.f;

#pragma unroll
        for (int kc = 0; kc < 8; kc++) {
#pragma unroll
            for (int nt = 0; nt < 4; nt++) {
                mma_f16(acc[0][nt], wreg[kc][0], hq[kc][nt][0], hq[kc][nt][1]);
                mma_f16(acc[1][nt], wreg[kc][1], hq[kc][nt][0], hq[kc][nt][1]);
            }
        }

#pragma unroll
        for (int mt = 0; mt < 2; mt++)
#pragma unroll
            for (int jh = 0; jh < 2; jh++) {
                int r = mt*16 + jh*8 + lr;
#pragma unroll
                for (int nt = 0; nt < 4; nt++) {
                    int n = nt*8 + lc*2;
                    *(float2*)(part + kg*PQ + r*36 + n) =
                        make_float2(acc[mt][nt][jh*2 + 0], acc[mt][nt][jh*2 + 1]);
                }
            }
        __syncthreads();

        float ga[4];
#pragma unroll
        for (int g = 0; g < 4; g++) {
            int roff = (g*8 + uu)*36 + b;
            float s = 0.f;
#pragma unroll
            for (int q = 0; q < 8; q++) s += part[q*PQ + roff];
            ga[g] = s + sXG[b*32 + g*8 + uu];
        }
        float ig = sigm(ga[0]);
        float fg = sigm(ga[1]);
        float gg = tanhf(ga[2]);
        float og = sigm(ga[3]);
        c_state = fg * c_state + ig * gg;
        float hval = og * tanhf(c_state);

        g_h16[(1 - rp)*32768 + w_idx] = __float2half_rn(hval);
        sHT[uu*33 + b] = hval;
        __syncthreads();

        {
            int b_ = tid >> 3, uo = tid & 7;
            hseq[((size_t)b_ * Tt + t) * Hh + u0 + uo] = sHT[uo*33 + b_];
        }

        if (tid == 0) {
            __threadfence();
            atomicAdd(&g_cnt, 1u);
            bar += NCTA;
            while (*((volatile unsigned int*)&g_cnt) < bar) { __nanosleep(40); }
            __threadfence();
        }
        __syncthreads();
    }
}

// ---------------- LayerNorm -> GELU ----------------
__global__ void ln_gelu_kernel(const float* __restrict__ X, const float* __restrict__ w,
                               const float* __restrict__ bv, float* __restrict__ Y)
{
    __shared__ float red[2][8];
    const int row = blockIdx.x;
    const int tid = threadIdx.x;
    float4 v = ((const float4*)(X + (size_t)row * Hh))[tid];
    float s = v.x + v.y + v.z + v.w;
    float q = v.x*v.x + v.y*v.y + v.z*v.z + v.w*v.w;
    int lane = tid & 31, wid = tid >> 5;
#pragma unroll
    for (int o = 16; o; o >>= 1) {
        s += __shfl_xor_sync(0xffffffffu, s, o);
        q += __shfl_xor_sync(0xffffffffu, q, o);
    }
    if (lane == 0) { red[0][wid] = s; red[1][wid] = q; }
    __syncthreads();
    if (wid == 0) {
        s = (lane < 8) ? red[0][lane] : 0.f;
        q = (lane < 8) ? red[1][lane] : 0.f;
#pragma unroll
        for (int o = 4; o; o >>= 1) {
            s += __shfl_xor_sync(0xffffffffu, s, o);
            q += __shfl_xor_sync(0xffffffffu, q, o);
        }
        if (lane == 0) { red[0][0] = s; red[1][0] = q; }
    }
    __syncthreads();
    float mu  = red[0][0] * (1.f / Hh);
    float var = red[1][0] * (1.f / Hh) - mu * mu;
    float rstd = rsqrtf(var + 1e-5f);
    float4 wv = ((const float4*)w)[tid];
    float4 bb = ((const float4*)bv)[tid];
    float4 y;
    y.x = gelu_exact((v.x - mu) * rstd * wv.x + bb.x);
    y.y = gelu_exact((v.y - mu) * rstd * wv.y + bb.y);
    y.z = gelu_exact((v.z - mu) * rstd * wv.z + bb.z);
    y.w = gelu_exact((v.w - mu) * rstd * wv.w + bb.w);
    ((float4*)(Y + (size_t)row * Hh))[tid] = y;
}

// ---------------- GELU -> LayerNorm ----------------
__global__ void gelu_ln_kernel(const float* __restrict__ X, const float* __restrict__ w,
                               const float* __restrict__ bv, float* __restrict__ Y)
{
    __shared__ float red[2][8];
    const int row = blockIdx.x;
    const int tid = threadIdx.x;
    float4 v = ((const float4*)(X + (size_t)row * Hh))[tid];
    v.x = gelu_exact(v.x); v.y = gelu_exact(v.y);
    v.z = gelu_exact(v.z); v.w = gelu_exact(v.w);
    float s = v.x + v.y + v.z + v.w;
    float q = v.x*v.x + v.y*v.y + v.z*v.z + v.w*v.w;
    int lane = tid & 31, wid = tid >> 5;
#pragma unroll
    for (int o = 16; o; o >>= 1) {
        s += __shfl_xor_sync(0xffffffffu, s, o);
        q += __shfl_xor_sync(0xffffffffu, q, o);
    }
    if (lane == 0) { red[0][wid] = s; red[1][wid] = q; }
    __syncthreads();
    if (wid == 0) {
        s = (lane < 8) ? red[0][lane] : 0.f;
        q = (lane < 8) ? red[1][lane] : 0.f;
#pragma unroll
        for (int o = 4; o; o >>= 1) {
            s += __shfl_xor_sync(0xffffffffu, s, o);
            q += __shfl_xor_sync(0xffffffffu, q, o);
        }
        if (lane == 0) { red[0][0] = s; red[1][0] = q; }
    }
    __syncthreads();
    float mu  = red[0][0] * (1.f / Hh);
    float var = red[1][0] * (1.f / Hh) - mu * mu;
    float rstd = rsqrtf(var + 1e-5f);
    float4 wv = ((const float4*)w)[tid];
    float4 bb = ((const float4*)bv)[tid];
    float4 y;
    y.x = (v.x - mu) * rstd * wv.x + bb.x;
    y.y = (v.y - mu) * rstd * wv.y + bb.y;
    y.z = (v.z - mu) * rstd * wv.z + bb.z;
    y.w = (v.w - mu) * rstd * wv.w + bb.w;
    ((float4*)(Y + (size_t)row * Hh))[tid] = y;
}

// ---------------- driver ----------------
extern "C" void kernel_launch(void* const* d_in, const int* in_sizes, int n_in,
                              void* d_out, int out_size)
{
    const float* bone  = (const float*)d_in[0];
    const float* W_ih0 = (const float*)d_in[1];
    const float* W_hh0 = (const float*)d_in[2];
    const float* b_ih0 = (const float*)d_in[3];
    const float* b_hh0 = (const float*)d_in[4];
    const float* W_ih1 = (const float*)d_in[5];
    const float* W_hh1 = (const float*)d_in[6];
    const float* b_ih1 = (const float*)d_in[7];
    const float* b_hh1 = (const float*)d_in[8];
    const float* ln1w  = (const float*)d_in[9];
    const float* ln1b  = (const float*)d_in[10];
    const float* linw  = (const float*)d_in[11];
    const float* linb  = (const float*)d_in[12];
    const float* ln2w  = (const float*)d_in[13];
    const float* ln2b  = (const float*)d_in[14];
    float* out = (float*)d_out;

    float *xg = nullptr, *hseq = nullptr;
    unsigned *wf0 = nullptr, *wf1 = nullptr;
    cudaGetSymbolAddress((void**)&xg, g_xg);
    cudaGetSymbolAddress((void**)&hseq, g_hseq);
    cudaGetSymbolAddress((void**)&wf0, g_wf0);
    cudaGetSymbolAddress((void**)&wf1, g_wf1);
    float* act = xg;
    float* lin = xg + (size_t)BT * Hh;

    cudaFuncSetAttribute(lstm_scan, cudaFuncAttributeMaxDynamicSharedMemorySize, SCAN_SMEM);

    dim3 gemm_g4(G4/128, BT/128);
    dim3 gemm_h(Hh/128, BT/128);

    prep_whh_f16<<<8192, 256>>>(W_hh0, wf0);
    prep_whh_f16<<<8192, 256>>>(W_hh1, wf1);

    // layer 0
    gemm_f16_nt_bias<<<gemm_g4, 256>>>(bone, W_ih0, b_ih0, b_hh0, xg, BT, G4, Dd);
    reset_scan_state<<<64, 256>>>();
    lstm_scan<<<NCTA, 256, SCAN_SMEM>>>(wf0, xg, hseq);

    // layer 1
    gemm_f16_nt_bias<<<gemm_g4, 256>>>(hseq, W_ih1, b_ih1, b_hh1, xg, BT, G4, Hh);
    reset_scan_state<<<64, 256>>>();
    lstm_scan<<<NCTA, 256, SCAN_SMEM>>>(wf1, xg, hseq);

    // post: LN -> GELU -> Linear -> GELU -> LN
    ln_gelu_kernel<<<BT, 256>>>(hseq, ln1w, ln1b, act);
    gemm_f16_nt_bias<<<gemm_h, 256>>>(act, linw, linb, nullptr, lin, BT, Hh, Hh);
    gelu_ln_kernel<<<BT, 256>>>(lin, ln2w, ln2b, out);
}